// round 7
// baseline (speedup 1.0000x reference)
#include <cuda_runtime.h>
#include <math.h>
#include <stdint.h>

#define D_MODEL 512
#define HEADS   8
#define DKH     64
#define SEQ     2048
#define BATCH   4
#define D_FF    1024
#define NROWS   (BATCH*SEQ)   // 8192

// Scratch (static device arrays — no allocation at runtime)
__device__ float g_x [NROWS * D_MODEL];   // running residual stream
__device__ float g_xn[NROWS * D_MODEL];   // layernorm output
__device__ float g_h [NROWS * D_FF];      // FFN hidden

// ---------------------------------------------------------------------------
// tf32 helpers
// ---------------------------------------------------------------------------
__device__ __forceinline__ uint32_t f2tf(float x) {
    uint32_t r;
    asm("cvt.rna.tf32.f32 %0, %1;" : "=r"(r) : "f"(x));
    return r;
}

// D += A(16x8) * B(8x8); A row-major, B col-major.
// a0=A[g][t], a1=A[g+8][t], a2=A[g][t+4], a3=A[g+8][t+4]
// b0=B[t][g], b1=B[t+4][g];  c0=C[g][2t], c1=C[g][2t+1], c2/c3 rows +8
__device__ __forceinline__ void mma_tf32(float c[4],
                                         uint32_t a0, uint32_t a1, uint32_t a2, uint32_t a3,
                                         uint32_t b0, uint32_t b1) {
    asm volatile(
        "mma.sync.aligned.m16n8k8.row.col.f32.tf32.tf32.f32 "
        "{%0,%1,%2,%3}, {%4,%5,%6,%7}, {%8,%9}, {%0,%1,%2,%3};\n"
        : "+f"(c[0]), "+f"(c[1]), "+f"(c[2]), "+f"(c[3])
        : "r"(a0), "r"(a1), "r"(a2), "r"(a3), "r"(b0), "r"(b1));
}

// ---------------------------------------------------------------------------
// LayerNorm: one block per row (512 elems), 128 threads x float4
// ---------------------------------------------------------------------------
__global__ void ln_kernel(const float* __restrict__ x,
                          const float* __restrict__ gamma,
                          const float* __restrict__ beta,
                          float* __restrict__ y) {
    int row = blockIdx.x;
    int t   = threadIdx.x;
    const float4* xr = (const float4*)(x + (size_t)row * D_MODEL);
    float4 v = xr[t];
    float s  = v.x + v.y + v.z + v.w;
    float ss = v.x*v.x + v.y*v.y + v.z*v.z + v.w*v.w;
    #pragma unroll
    for (int o = 16; o > 0; o >>= 1) {
        s  += __shfl_xor_sync(0xffffffffu, s,  o);
        ss += __shfl_xor_sync(0xffffffffu, ss, o);
    }
    __shared__ float as[4], ass[4];
    int w = t >> 5;
    if ((t & 31) == 0) { as[w] = s; ass[w] = ss; }
    __syncthreads();
    s  = as[0]  + as[1]  + as[2]  + as[3];
    ss = ass[0] + ass[1] + ass[2] + ass[3];
    float mu  = s * (1.0f / D_MODEL);
    float var = ss * (1.0f / D_MODEL) - mu * mu;
    float rs  = rsqrtf(var + 1e-5f);
    float4 g4 = ((const float4*)gamma)[t];
    float4 b4 = ((const float4*)beta)[t];
    float4 o4;
    o4.x = (v.x - mu) * rs * g4.x + b4.x;
    o4.y = (v.y - mu) * rs * g4.y + b4.y;
    o4.z = (v.z - mu) * rs * g4.z + b4.z;
    o4.w = (v.w - mu) * rs * g4.w + b4.w;
    ((float4*)(y + (size_t)row * D_MODEL))[t] = o4;
}

// ---------------------------------------------------------------------------
// Flash attention, tf32 mma. BM=128, 256 threads (8 warps), warp tile 16x64.
// Smem layouts (uint2 = packed tf32 pairs), all mainloop reads 2-phase max:
//   Qst[r][ks*4+t]  = {Q[r][8ks+t],  Q[r][8ks+t+4]}   stride 36 (persistent)
//   Kp [n][ks*4+t]  = {K[n][8ks+t],  K[n][8ks+t+4]}   stride 36
//   Vp [4a+c][col]  = {V[8a+c][col], V[8a+c+4][col]}  stride 68
//   Pp [r][4nf+t]   = {P[r][8nf+2t], P[r][8nf+2t+1]}  stride 38
// K and V come from ONE set of LDG+cvt (same source tile).
// ---------------------------------------------------------------------------
#define BM   128
#define QS_S 36
#define KP_S 36
#define VP_S 68
#define PP_S 38
#define ATTN_SMEM_BYTES ((128*QS_S + 64*KP_S + 32*VP_S + 128*PP_S) * 8)

__global__ __launch_bounds__(256, 2)
void attn_mma_kernel(const float* __restrict__ Q,
                     const float* __restrict__ KV,
                     const int*   __restrict__ mask,   // may be null
                     const float* __restrict__ res,
                     float* __restrict__ out) {
    extern __shared__ uint2 sm2[];
    uint2* Qst = sm2;
    uint2* Kp  = Qst + 128 * QS_S;
    uint2* Vp  = Kp  + 64 * KP_S;
    uint2* Pp  = Vp  + 32 * VP_S;
    uint32_t* PpU = (uint32_t*)Pp;   // u32 stride = 2*PP_S = 76

    const int q0   = blockIdx.x * BM;
    const int h    = blockIdx.y;
    const int b    = blockIdx.z;
    const int tid  = threadIdx.x;
    const int lane = tid & 31;
    const int warp = tid >> 5;
    const int g    = lane >> 2;
    const int tig  = lane & 3;
    const int wrow = warp * 16;

    // ---- Stage Q [128 x 64] into packed pairs-in-row layout ----
    {
        int r = tid >> 1, hh = tid & 1;
        const float* src = Q + ((size_t)(b * SEQ + q0 + r)) * D_MODEL + h * DKH + hh * 32;
        uint2* dst = Qst + r * QS_S + hh * 16;
        #pragma unroll
        for (int c = 0; c < 4; c++) {
            float4 v0 = *(const float4*)(src + c * 8);
            float4 v1 = *(const float4*)(src + c * 8 + 4);
            uint4* d = (uint4*)(dst + c * 4);
            d[0] = make_uint4(f2tf(v0.x), f2tf(v1.x), f2tf(v0.y), f2tf(v1.y));
            d[1] = make_uint4(f2tf(v0.z), f2tf(v1.z), f2tf(v0.w), f2tf(v1.w));
        }
    }

    float oacc[8][4];
    #pragma unroll
    for (int i = 0; i < 8; i++)
        #pragma unroll
        for (int j = 0; j < 4; j++) oacc[i][j] = 0.0f;

    float mrow[2] = {-INFINITY, -INFINITY};
    float lrow[2] = {0.0f, 0.0f};

    // combined loader coords (one 2-row x 8-col unit per thread)
    const int lcc = tid & 7;          // col chunk (8 cols)
    const int lc  = (tid >> 3) & 3;   // row-within-8 (0..3)
    const int la  = tid >> 5;         // 8-row block (0..7)

    for (int kt = 0; kt < SEQ / 64; kt++) {
        const int k0 = kt * 64;
        __syncthreads();   // Qst ready (1st iter) / Kp,Vp consumed (later iters)

        // ---- ONE loader fills both Kp and Vp from the same gmem tile ----
        {
            int r0 = 8 * la + lc;
            const float* s0 = KV + ((size_t)(b * SEQ + k0 + r0)) * D_MODEL + h * DKH + lcc * 8;
            const float* s1 = s0 + (size_t)4 * D_MODEL;   // row r0+4
            float4 f0 = *(const float4*)s0;
            float4 f1 = *(const float4*)(s0 + 4);
            float4 f2 = *(const float4*)s1;
            float4 f3 = *(const float4*)(s1 + 4);
            uint32_t t0[8] = { f2tf(f0.x), f2tf(f0.y), f2tf(f0.z), f2tf(f0.w),
                               f2tf(f1.x), f2tf(f1.y), f2tf(f1.z), f2tf(f1.w) };
            uint32_t t1[8] = { f2tf(f2.x), f2tf(f2.y), f2tf(f2.z), f2tf(f2.w),
                               f2tf(f3.x), f2tf(f3.y), f2tf(f3.z), f2tf(f3.w) };
            uint4* dk0 = (uint4*)(Kp + r0 * KP_S + lcc * 4);
            dk0[0] = make_uint4(t0[0], t0[4], t0[1], t0[5]);
            dk0[1] = make_uint4(t0[2], t0[6], t0[3], t0[7]);
            uint4* dk1 = (uint4*)(Kp + (r0 + 4) * KP_S + lcc * 4);
            dk1[0] = make_uint4(t1[0], t1[4], t1[1], t1[5]);
            dk1[1] = make_uint4(t1[2], t1[6], t1[3], t1[7]);
            uint4* dv = (uint4*)(Vp + (la * 4 + lc) * VP_S + lcc * 8);
            dv[0] = make_uint4(t0[0], t1[0], t0[1], t1[1]);
            dv[1] = make_uint4(t0[2], t1[2], t0[3], t1[3]);
            dv[2] = make_uint4(t0[4], t1[4], t0[5], t1[5]);
            dv[3] = make_uint4(t0[6], t1[6], t0[7], t1[7]);
        }
        __syncthreads();

        // ---- S = Q K^T : warp 16x64 ----
        float sacc[8][4];
        #pragma unroll
        for (int i = 0; i < 8; i++)
            #pragma unroll
            for (int j = 0; j < 4; j++) sacc[i][j] = 0.0f;

        #pragma unroll
        for (int ks = 0; ks < 8; ks++) {
            uint2 qa = Qst[(wrow + g)     * QS_S + ks * 4 + tig];
            uint2 qb = Qst[(wrow + 8 + g) * QS_S + ks * 4 + tig];
            #pragma unroll
            for (int nf = 0; nf < 8; nf++) {
                uint2 kb = Kp[(nf * 8 + g) * KP_S + ks * 4 + tig];
                mma_tf32(sacc[nf], qa.x, qb.x, qa.y, qb.y, kb.x, kb.y);
            }
        }
        #pragma unroll
        for (int i = 0; i < 8; i++)
            #pragma unroll
            for (int j = 0; j < 4; j++) sacc[i][j] *= 0.125f;

        if (mask != nullptr) {
            int qr = q0 + wrow + g;
            const int* mr0 = mask + ((size_t)b * SEQ + qr) * SEQ + k0;
            const int* mr1 = mr0 + (size_t)8 * SEQ;
            #pragma unroll
            for (int nf = 0; nf < 8; nf++) {
                int kc = nf * 8 + 2 * tig;
                int2 mA = *(const int2*)(mr0 + kc);
                int2 mB = *(const int2*)(mr1 + kc);
                if (mA.x == 0) sacc[nf][0] = -1e9f;
                if (mA.y == 0) sacc[nf][1] = -1e9f;
                if (mB.x == 0) sacc[nf][2] = -1e9f;
                if (mB.y == 0) sacc[nf][3] = -1e9f;
            }
        }

        // ---- online softmax, 2 row-streams (rows g / g+8), quad-reduced ----
        float tm0 = -INFINITY, tm1 = -INFINITY;
        #pragma unroll
        for (int nf = 0; nf < 8; nf++) {
            tm0 = fmaxf(tm0, fmaxf(sacc[nf][0], sacc[nf][1]));
            tm1 = fmaxf(tm1, fmaxf(sacc[nf][2], sacc[nf][3]));
        }
        tm0 = fmaxf(tm0, __shfl_xor_sync(0xffffffffu, tm0, 1));
        tm0 = fmaxf(tm0, __shfl_xor_sync(0xffffffffu, tm0, 2));
        tm1 = fmaxf(tm1, __shfl_xor_sync(0xffffffffu, tm1, 1));
        tm1 = fmaxf(tm1, __shfl_xor_sync(0xffffffffu, tm1, 2));

        float mn0 = fmaxf(mrow[0], tm0), mn1 = fmaxf(mrow[1], tm1);
        float c0 = __expf(mrow[0] - mn0), c1 = __expf(mrow[1] - mn1);
        float s0 = 0.0f, s1 = 0.0f;
        #pragma unroll
        for (int nf = 0; nf < 8; nf++) {
            float p0 = __expf(sacc[nf][0] - mn0);
            float p1 = __expf(sacc[nf][1] - mn0);
            float p2 = __expf(sacc[nf][2] - mn1);
            float p3 = __expf(sacc[nf][3] - mn1);
            s0 += p0 + p1; s1 += p2 + p3;
            sacc[nf][0] = p0; sacc[nf][1] = p1;
            sacc[nf][2] = p2; sacc[nf][3] = p3;
        }
        s0 += __shfl_xor_sync(0xffffffffu, s0, 1);
        s0 += __shfl_xor_sync(0xffffffffu, s0, 2);
        s1 += __shfl_xor_sync(0xffffffffu, s1, 1);
        s1 += __shfl_xor_sync(0xffffffffu, s1, 2);

        mrow[0] = mn0; mrow[1] = mn1;
        lrow[0] = lrow[0] * c0 + s0;
        lrow[1] = lrow[1] * c1 + s1;

        #pragma unroll
        for (int df = 0; df < 8; df++) {
            oacc[df][0] *= c0; oacc[df][1] *= c0;
            oacc[df][2] *= c1; oacc[df][3] *= c1;
        }

        // ---- store P (tf32, accumulator-pair layout), warp-private rows ----
        {
            int rp = wrow + g;
            #pragma unroll
            for (int nf = 0; nf < 8; nf++) {
                Pp[rp       * PP_S + nf * 4 + tig] =
                    make_uint2(f2tf(sacc[nf][0]), f2tf(sacc[nf][1]));
                Pp[(rp + 8) * PP_S + nf * 4 + tig] =
                    make_uint2(f2tf(sacc[nf][2]), f2tf(sacc[nf][3]));
            }
        }
        __syncwarp();

        // ---- O += P V ----
        #pragma unroll
        for (int ks = 0; ks < 8; ks++) {
            const uint32_t* base = PpU + (wrow + g) * (2 * PP_S) + ks * 8 + tig;
            uint32_t pa0 = base[0];
            uint32_t pa1 = base[8 * 2 * PP_S];
            uint32_t pa2 = base[4];
            uint32_t pa3 = base[8 * 2 * PP_S + 4];
            #pragma unroll
            for (int df = 0; df < 8; df++) {
                uint2 vb = Vp[(ks * 4 + tig) * VP_S + df * 8 + g];
                mma_tf32(oacc[df], pa0, pa1, pa2, pa3, vb.x, vb.y);
            }
        }
    }

    // ---- epilogue: normalize + residual ----
    float inv0 = 1.0f / lrow[0], inv1 = 1.0f / lrow[1];
    int r = q0 + wrow + g;
    #pragma unroll
    for (int df = 0; df < 8; df++) {
        size_t idx0 = ((size_t)(b * SEQ + r)) * D_MODEL + h * DKH + df * 8 + 2 * tig;
        size_t idx1 = idx0 + (size_t)8 * D_MODEL;
        float2 ra = *(const float2*)(res + idx0);
        float2 rb = *(const float2*)(res + idx1);
        float2 oa, ob;
        oa.x = ra.x + oacc[df][0] * inv0;
        oa.y = ra.y + oacc[df][1] * inv0;
        ob.x = rb.x + oacc[df][2] * inv1;
        ob.y = rb.y + oacc[df][3] * inv1;
        *(float2*)(out + idx0) = oa;
        *(float2*)(out + idx1) = ob;
    }
}

// ---------------------------------------------------------------------------
// tf32 mma GEMM: C[M,N] = A[M,K] @ B[K,N] + bias (+ReLU) (+res).
// Block 128x64, BK=32, 256 threads (8 warps), warp tile 16x64.
// ---------------------------------------------------------------------------
#define GA_S 20   // uint2 per A row (16 + pad)
#define GB_S 68   // uint2 per B row-pair (64 + pad; 2-phase reads)

template<bool RELU, bool RES>
__global__ __launch_bounds__(256, 2)
void gemm_mma(const float* __restrict__ A,
              const float* __restrict__ B,
              const float* __restrict__ bias,
              const float* __restrict__ res,
              float* __restrict__ C,
              int M, int N, int K) {
    __shared__ uint2 Ap[128 * GA_S];
    __shared__ uint2 Bp[16 * GB_S];

    const int n0   = blockIdx.x * 64;
    const int m0   = blockIdx.y * 128;
    const int tid  = threadIdx.x;
    const int lane = tid & 31;
    const int warp = tid >> 5;
    const int g    = lane >> 2;
    const int tig  = lane & 3;
    const int wrow = warp * 16;

    // loader coords
    const int ar  = tid >> 1, ah = tid & 1;          // A: row, col-half
    const int bcq = tid & 15, brp = tid >> 4;        // B: col-quad, row-pair
    const int bk  = 8 * (brp >> 2) + (brp & 3);      // B base row within BK

    float acc[8][4];
    #pragma unroll
    for (int i = 0; i < 8; i++)
        #pragma unroll
        for (int j = 0; j < 4; j++) acc[i][j] = 0.0f;

    for (int k0 = 0; k0 < K; k0 += 32) {
        __syncthreads();
        // A fill: thread handles row ar, cols [16*ah, 16*ah+16)
        {
            const float* src = A + (size_t)(m0 + ar) * K + k0 + ah * 16;
            uint2* dst = Ap + ar * GA_S + ah * 8;
            #pragma unroll
            for (int c = 0; c < 2; c++) {
                float4 v0 = *(const float4*)(src + c * 8);
                float4 v1 = *(const float4*)(src + c * 8 + 4);
                uint4* d = (uint4*)(dst + c * 4);
                d[0] = make_uint4(f2tf(v0.x), f2tf(v1.x), f2tf(v0.y), f2tf(v1.y));
                d[1] = make_uint4(f2tf(v0.z), f2tf(v1.z), f2tf(v0.w), f2tf(v1.w));
            }
        }
        // B fill: rows (bk, bk+4), cols [4*bcq, 4*bcq+4)
        {
            const float* s0 = B + (size_t)(k0 + bk) * N + n0 + bcq * 4;
            const float* s1 = s0 + (size_t)4 * N;
            float4 f0 = *(const float4*)s0;
            float4 f1 = *(const float4*)s1;
            uint4* d = (uint4*)(Bp + brp * GB_S + bcq * 4);
            d[0] = make_uint4(f2tf(f0.x), f2tf(f1.x), f2tf(f0.y), f2tf(f1.y));
            d[1] = make_uint4(f2tf(f0.z), f2tf(f1.z), f2tf(f0.w), f2tf(f1.w));
        }
        __syncthreads();

        #pragma unroll
        for (int ks = 0; ks < 4; ks++) {
            uint2 aa = Ap[(wrow + g)     * GA_S + ks * 4 + tig];
            uint2 ab = Ap[(wrow + 8 + g) * GA_S + ks * 4 + tig];
            #pragma unroll
            for (int nf = 0; nf < 8; nf++) {
                uint2 bb = Bp[(ks * 4 + tig) * GB_S + nf * 8 + g];
                mma_tf32(acc[nf], aa.x, ab.x, aa.y, ab.y, bb.x, bb.y);
            }
        }
    }

    const int row0 = m0 + wrow + g;
    #pragma unroll
    for (int nf = 0; nf < 8; nf++) {
        int col = n0 + nf * 8 + 2 * tig;
        float2 bi = *(const float2*)(bias + col);
        size_t idx0 = (size_t)row0 * N + col;
        size_t idx1 = idx0 + (size_t)8 * N;
        float2 va, vb;
        va.x = acc[nf][0] + bi.x; va.y = acc[nf][1] + bi.y;
        vb.x = acc[nf][2] + bi.x; vb.y = acc[nf][3] + bi.y;
        if (RELU) {
            va.x = fmaxf(va.x, 0.0f); va.y = fmaxf(va.y, 0.0f);
            vb.x = fmaxf(vb.x, 0.0f); vb.y = fmaxf(vb.y, 0.0f);
        }
        if (RES) {
            float2 ra = *(const float2*)(res + idx0);
            float2 rb = *(const float2*)(res + idx1);
            va.x += ra.x; va.y += ra.y;
            vb.x += rb.x; vb.y += rb.y;
        }
        *(float2*)(C + idx0) = va;
        *(float2*)(C + idx1) = vb;
    }
}

// ---------------------------------------------------------------------------
extern "C" void kernel_launch(void* const* d_in, const int* in_sizes, int n_in,
                              void* d_out, int out_size) {
    const float* x    = (const float*)d_in[0];
    const float* enc  = (const float*)d_in[1];
    const int*   mask = (const int*)  d_in[2];
    const float* ln1g = (const float*)d_in[3];
    const float* ln1b = (const float*)d_in[4];
    const float* ln2g = (const float*)d_in[5];
    const float* ln2b = (const float*)d_in[6];
    const float* ln3g = (const float*)d_in[7];
    const float* ln3b = (const float*)d_in[8];
    const float* W1   = (const float*)d_in[9];
    const float* b1   = (const float*)d_in[10];
    const float* W2   = (const float*)d_in[11];
    const float* b2   = (const float*)d_in[12];
    float* out = (float*)d_out;

    float *gx, *gxn, *gh;
    cudaGetSymbolAddress((void**)&gx,  g_x);
    cudaGetSymbolAddress((void**)&gxn, g_xn);
    cudaGetSymbolAddress((void**)&gh,  g_h);

    cudaFuncSetAttribute(attn_mma_kernel,
                         cudaFuncAttributeMaxDynamicSharedMemorySize,
                         ATTN_SMEM_BYTES);

    dim3 attn_grid(SEQ / BM, HEADS, BATCH);

    // 1) x1 = LN1(x); x' = x + selfattn(x1, mask)
    ln_kernel<<<NROWS, 128>>>(x, ln1g, ln1b, gxn);
    attn_mma_kernel<<<attn_grid, 256, ATTN_SMEM_BYTES>>>(gxn, gxn, mask, x, gx);

    // 2) x1 = LN2(x'); x'' = x' + crossattn(x1, enc)
    ln_kernel<<<NROWS, 128>>>(gx, ln2g, ln2b, gxn);
    attn_mma_kernel<<<attn_grid, 256, ATTN_SMEM_BYTES>>>(gxn, enc, nullptr, gx, gx);

    // 3) x1 = LN3(x''); out = x'' + relu(x1 W1 + b1) W2 + b2
    ln_kernel<<<NROWS, 128>>>(gx, ln3g, ln3b, gxn);
    gemm_mma<true,  false><<<dim3(D_FF / 64,    NROWS / 128), 256>>>(
        gxn, W1, b1, nullptr, gh, NROWS, D_FF, D_MODEL);
    gemm_mma<false, true ><<<dim3(D_MODEL / 64, NROWS / 128), 256>>>(
        gh, W2, b2, gx, out, NROWS, D_MODEL, D_FF);
}

// round 8
// speedup vs baseline: 1.4495x; 1.4495x over previous
#include <cuda_runtime.h>
#include <cuda_fp16.h>
#include <math.h>
#include <stdint.h>

#define D_MODEL 512
#define HEADS   8
#define DKH     64
#define SEQ     2048
#define BATCH   4
#define D_FF    1024
#define NROWS   (BATCH*SEQ)   // 8192

// Scratch (static device arrays — no allocation at runtime)
__device__ float g_x [NROWS * D_MODEL];   // running residual stream
__device__ float g_xn[NROWS * D_MODEL];   // layernorm output
__device__ float g_h [NROWS * D_FF];      // FFN hidden

// ---------------------------------------------------------------------------
// fp16 helpers
// ---------------------------------------------------------------------------
__device__ __forceinline__ uint32_t f2h2(float lo, float hi) {
    __half2 h = __floats2half2_rn(lo, hi);   // .x (low 16b) = lo
    return *(uint32_t*)&h;
}

// D += A(16x16) * B(16x8); fp16 in, fp32 accum.
// a0={A[g][2t],A[g][2t+1]}  a1=rows+8  a2={A[g][2t+8],+9}  a3=rows+8 hi
// b0={B[2t][g],B[2t+1][g]}  b1={B[2t+8][g],B[2t+9][g]}
// c0=C[g][2t], c1=C[g][2t+1], c2/c3 rows +8
__device__ __forceinline__ void mma_f16(float c[4],
                                        uint32_t a0, uint32_t a1, uint32_t a2, uint32_t a3,
                                        uint32_t b0, uint32_t b1) {
    asm volatile(
        "mma.sync.aligned.m16n8k16.row.col.f32.f16.f16.f32 "
        "{%0,%1,%2,%3}, {%4,%5,%6,%7}, {%8,%9}, {%0,%1,%2,%3};\n"
        : "+f"(c[0]), "+f"(c[1]), "+f"(c[2]), "+f"(c[3])
        : "r"(a0), "r"(a1), "r"(a2), "r"(a3), "r"(b0), "r"(b1));
}

// ---------------------------------------------------------------------------
// LayerNorm: one block per row (512 elems), 128 threads x float4
// ---------------------------------------------------------------------------
__global__ void ln_kernel(const float* __restrict__ x,
                          const float* __restrict__ gamma,
                          const float* __restrict__ beta,
                          float* __restrict__ y) {
    int row = blockIdx.x;
    int t   = threadIdx.x;
    const float4* xr = (const float4*)(x + (size_t)row * D_MODEL);
    float4 v = xr[t];
    float s  = v.x + v.y + v.z + v.w;
    float ss = v.x*v.x + v.y*v.y + v.z*v.z + v.w*v.w;
    #pragma unroll
    for (int o = 16; o > 0; o >>= 1) {
        s  += __shfl_xor_sync(0xffffffffu, s,  o);
        ss += __shfl_xor_sync(0xffffffffu, ss, o);
    }
    __shared__ float as[4], ass[4];
    int w = t >> 5;
    if ((t & 31) == 0) { as[w] = s; ass[w] = ss; }
    __syncthreads();
    s  = as[0]  + as[1]  + as[2]  + as[3];
    ss = ass[0] + ass[1] + ass[2] + ass[3];
    float mu  = s * (1.0f / D_MODEL);
    float var = ss * (1.0f / D_MODEL) - mu * mu;
    float rs  = rsqrtf(var + 1e-5f);
    float4 g4 = ((const float4*)gamma)[t];
    float4 b4 = ((const float4*)beta)[t];
    float4 o4;
    o4.x = (v.x - mu) * rs * g4.x + b4.x;
    o4.y = (v.y - mu) * rs * g4.y + b4.y;
    o4.z = (v.z - mu) * rs * g4.z + b4.z;
    o4.w = (v.w - mu) * rs * g4.w + b4.w;
    ((float4*)(y + (size_t)row * D_MODEL))[t] = o4;
}

// ---------------------------------------------------------------------------
// Flash attention, fp16 mma (m16n8k16). BM=128, 256 threads, warp tile 16x64.
// Smem (uint2 entries; each u32 is an fp16 pair):
//  Qp[r][ks*4+t] = {h2(Q[r][16ks+2t],+1),   h2(Q[r][16ks+2t+8],+9)}   stride 20
//  Kp[n][ks*4+t] = same pairs-in-row packing of K                      stride 20
//  Vp[(ks*4+t)][c] = {h2(V[16ks+2t][c],V[+1][c]), h2(V[+8][c],V[+9][c])} stride 68
//  Pp[r][ks*4+t] = {h2(P[r][16ks+2t],+1),   h2(P[r][16ks+2t+8],+9)}   stride 20
// Q is pre-scaled by 1/8 at staging (folds softmax scale into QK^T).
// ---------------------------------------------------------------------------
#define BM    128
#define QP_S  20
#define KP_S  20
#define VP_S  68
#define PP_S  20
#define ATTN_SMEM_BYTES ((128*QP_S + 64*KP_S + 16*VP_S + 128*PP_S) * 8)

__global__ __launch_bounds__(256, 2)
void attn_mma_kernel(const float* __restrict__ Q,
                     const float* __restrict__ KV,
                     const int*   __restrict__ mask,   // may be null
                     const float* __restrict__ res,
                     float* __restrict__ out) {
    extern __shared__ uint2 sm2[];
    uint2* Qp = sm2;
    uint2* Kp = Qp + 128 * QP_S;
    uint2* Vp = Kp + 64 * KP_S;
    uint2* Pp = Vp + 16 * VP_S;

    const int q0   = blockIdx.x * BM;
    const int h    = blockIdx.y;
    const int b    = blockIdx.z;
    const int tid  = threadIdx.x;
    const int lane = tid & 31;
    const int warp = tid >> 5;
    const int g    = lane >> 2;
    const int tig  = lane & 3;
    const int wrow = warp * 16;

    // ---- Stage Q [128 x 64], scaled by 1/8, packed fp16 pairs ----
    #pragma unroll
    for (int it = 0; it < 2; it++) {
        int i = tid + it * 256;
        int r = i >> 2, cc = i & 3;      // row, k16-chunk
        const float* src = Q + ((size_t)(b * SEQ + q0 + r)) * D_MODEL + h * DKH + cc * 16;
        float f[16];
        #pragma unroll
        for (int c = 0; c < 4; c++) {
            float4 v = *(const float4*)(src + c * 4);
            f[c*4+0] = v.x * 0.125f; f[c*4+1] = v.y * 0.125f;
            f[c*4+2] = v.z * 0.125f; f[c*4+3] = v.w * 0.125f;
        }
        uint2* dst = Qp + r * QP_S + cc * 4;
        uint4* d4 = (uint4*)dst;
        d4[0] = make_uint4(f2h2(f[0], f[1]), f2h2(f[8],  f[9]),
                           f2h2(f[2], f[3]), f2h2(f[10], f[11]));
        d4[1] = make_uint4(f2h2(f[4], f[5]), f2h2(f[12], f[13]),
                           f2h2(f[6], f[7]), f2h2(f[14], f[15]));
    }

    float oacc[8][4];
    #pragma unroll
    for (int i = 0; i < 8; i++)
        #pragma unroll
        for (int j = 0; j < 4; j++) oacc[i][j] = 0.0f;

    float mrow[2] = {-INFINITY, -INFINITY};
    float lrow[2] = {0.0f, 0.0f};

    // loader coords
    const int kr  = tid >> 2,  kcc = tid & 3;              // K: row, k16 chunk
    const int vcc = tid & 15;                              // V: col chunk (4 cols)
    const int vks = (tid >> 6) & 3, vtr = (tid >> 4) & 3;  // V: k16 chunk, row-in-group

    for (int kt = 0; kt < SEQ / 64; kt++) {
        const int k0 = kt * 64;
        __syncthreads();   // Qp ready (1st iter) / Kp,Vp consumed (later iters)

        // ---- K loader: 1 row x 16 cols per thread ----
        {
            const float* src = KV + ((size_t)(b * SEQ + k0 + kr)) * D_MODEL + h * DKH + kcc * 16;
            float f[16];
            #pragma unroll
            for (int c = 0; c < 4; c++) {
                float4 v = *(const float4*)(src + c * 4);
                f[c*4+0] = v.x; f[c*4+1] = v.y; f[c*4+2] = v.z; f[c*4+3] = v.w;
            }
            uint4* d4 = (uint4*)(Kp + kr * KP_S + kcc * 4);
            d4[0] = make_uint4(f2h2(f[0], f[1]), f2h2(f[8],  f[9]),
                               f2h2(f[2], f[3]), f2h2(f[10], f[11]));
            d4[1] = make_uint4(f2h2(f[4], f[5]), f2h2(f[12], f[13]),
                               f2h2(f[6], f[7]), f2h2(f[14], f[15]));
        }
        // ---- V loader: 4 rows (r0,r0+1,r0+8,r0+9) x 4 cols per thread ----
        {
            int r0 = vks * 16 + 2 * vtr;
            const float* s0 = KV + ((size_t)(b * SEQ + k0 + r0)) * D_MODEL + h * DKH + vcc * 4;
            float4 a0 = *(const float4*)s0;
            float4 a1 = *(const float4*)(s0 + (size_t)1 * D_MODEL);
            float4 a2 = *(const float4*)(s0 + (size_t)8 * D_MODEL);
            float4 a3 = *(const float4*)(s0 + (size_t)9 * D_MODEL);
            uint4* d4 = (uint4*)(Vp + (vks * 4 + vtr) * VP_S + vcc * 4);
            d4[0] = make_uint4(f2h2(a0.x, a1.x), f2h2(a2.x, a3.x),
                               f2h2(a0.y, a1.y), f2h2(a2.y, a3.y));
            d4[1] = make_uint4(f2h2(a0.z, a1.z), f2h2(a2.z, a3.z),
                               f2h2(a0.w, a1.w), f2h2(a2.w, a3.w));
        }
        __syncthreads();

        // ---- S = Q K^T : warp 16x64, 4 k16-steps x 8 n-frags ----
        float sacc[8][4];
        #pragma unroll
        for (int i = 0; i < 8; i++)
            #pragma unroll
            for (int j = 0; j < 4; j++) sacc[i][j] = 0.0f;

        #pragma unroll
        for (int ks = 0; ks < 4; ks++) {
            uint2 qa = Qp[(wrow + g)     * QP_S + ks * 4 + tig];
            uint2 qb = Qp[(wrow + 8 + g) * QP_S + ks * 4 + tig];
            #pragma unroll
            for (int nf = 0; nf < 8; nf++) {
                uint2 kb = Kp[(nf * 8 + g) * KP_S + ks * 4 + tig];
                mma_f16(sacc[nf], qa.x, qb.x, qa.y, qb.y, kb.x, kb.y);
            }
        }

        if (mask != nullptr) {
            int qr = q0 + wrow + g;
            const int* mr0 = mask + ((size_t)b * SEQ + qr) * SEQ + k0;
            const int* mr1 = mr0 + (size_t)8 * SEQ;
            #pragma unroll
            for (int nf = 0; nf < 8; nf++) {
                int kc = nf * 8 + 2 * tig;
                int2 mA = *(const int2*)(mr0 + kc);
                int2 mB = *(const int2*)(mr1 + kc);
                if (mA.x == 0) sacc[nf][0] = -1e9f;
                if (mA.y == 0) sacc[nf][1] = -1e9f;
                if (mB.x == 0) sacc[nf][2] = -1e9f;
                if (mB.y == 0) sacc[nf][3] = -1e9f;
            }
        }

        // ---- online softmax, 2 row-streams (rows g / g+8), quad-reduced ----
        float tm0 = -INFINITY, tm1 = -INFINITY;
        #pragma unroll
        for (int nf = 0; nf < 8; nf++) {
            tm0 = fmaxf(tm0, fmaxf(sacc[nf][0], sacc[nf][1]));
            tm1 = fmaxf(tm1, fmaxf(sacc[nf][2], sacc[nf][3]));
        }
        tm0 = fmaxf(tm0, __shfl_xor_sync(0xffffffffu, tm0, 1));
        tm0 = fmaxf(tm0, __shfl_xor_sync(0xffffffffu, tm0, 2));
        tm1 = fmaxf(tm1, __shfl_xor_sync(0xffffffffu, tm1, 1));
        tm1 = fmaxf(tm1, __shfl_xor_sync(0xffffffffu, tm1, 2));

        float mn0 = fmaxf(mrow[0], tm0), mn1 = fmaxf(mrow[1], tm1);
        float c0 = __expf(mrow[0] - mn0), c1 = __expf(mrow[1] - mn1);
        float s0 = 0.0f, s1 = 0.0f;
        #pragma unroll
        for (int nf = 0; nf < 8; nf++) {
            float p0 = __expf(sacc[nf][0] - mn0);
            float p1 = __expf(sacc[nf][1] - mn0);
            float p2 = __expf(sacc[nf][2] - mn1);
            float p3 = __expf(sacc[nf][3] - mn1);
            s0 += p0 + p1; s1 += p2 + p3;
            sacc[nf][0] = p0; sacc[nf][1] = p1;
            sacc[nf][2] = p2; sacc[nf][3] = p3;
        }
        s0 += __shfl_xor_sync(0xffffffffu, s0, 1);
        s0 += __shfl_xor_sync(0xffffffffu, s0, 2);
        s1 += __shfl_xor_sync(0xffffffffu, s1, 1);
        s1 += __shfl_xor_sync(0xffffffffu, s1, 2);

        mrow[0] = mn0; mrow[1] = mn1;
        lrow[0] = lrow[0] * c0 + s0;
        lrow[1] = lrow[1] * c1 + s1;

        #pragma unroll
        for (int df = 0; df < 8; df++) {
            oacc[df][0] *= c0; oacc[df][1] *= c0;
            oacc[df][2] *= c1; oacc[df][3] *= c1;
        }

        // ---- store P as fp16 pairs (warp-private rows) ----
        // Pp[r][ks*4+tig] = {h2(sacc[2ks][0..1]), h2(sacc[2ks+1][0..1])}
        #pragma unroll
        for (int ks = 0; ks < 4; ks++) {
            Pp[(wrow + g)     * PP_S + ks * 4 + tig] =
                make_uint2(f2h2(sacc[2*ks][0],   sacc[2*ks][1]),
                           f2h2(sacc[2*ks+1][0], sacc[2*ks+1][1]));
            Pp[(wrow + 8 + g) * PP_S + ks * 4 + tig] =
                make_uint2(f2h2(sacc[2*ks][2],   sacc[2*ks][3]),
                           f2h2(sacc[2*ks+1][2], sacc[2*ks+1][3]));
        }
        __syncwarp();

        // ---- O += P V ----
        #pragma unroll
        for (int ks = 0; ks < 4; ks++) {
            uint2 pa = Pp[(wrow + g)     * PP_S + ks * 4 + tig];
            uint2 pb = Pp[(wrow + 8 + g) * PP_S + ks * 4 + tig];
            #pragma unroll
            for (int df = 0; df < 8; df++) {
                uint2 vb = Vp[(ks * 4 + tig) * VP_S + df * 8 + g];
                mma_f16(oacc[df], pa.x, pb.x, pa.y, pb.y, vb.x, vb.y);
            }
        }
    }

    // ---- epilogue: normalize + residual ----
    float inv0 = 1.0f / lrow[0], inv1 = 1.0f / lrow[1];
    int r = q0 + wrow + g;
    #pragma unroll
    for (int df = 0; df < 8; df++) {
        size_t idx0 = ((size_t)(b * SEQ + r)) * D_MODEL + h * DKH + df * 8 + 2 * tig;
        size_t idx1 = idx0 + (size_t)8 * D_MODEL;
        float2 ra = *(const float2*)(res + idx0);
        float2 rb = *(const float2*)(res + idx1);
        float2 oa, ob;
        oa.x = ra.x + oacc[df][0] * inv0;
        oa.y = ra.y + oacc[df][1] * inv0;
        ob.x = rb.x + oacc[df][2] * inv1;
        ob.y = rb.y + oacc[df][3] * inv1;
        *(float2*)(out + idx0) = oa;
        *(float2*)(out + idx1) = ob;
    }
}

// ---------------------------------------------------------------------------
// fp16 mma GEMM: C[M,N] = A[M,K] @ B[K,N] + bias (+ReLU) (+res).
// Block 128x64, BK=32, 256 threads (8 warps), warp tile 16x64.
//  Ap[r][ks*4+t] pairs-in-row, stride 12;  Bp V-style row-pair packing, stride 68.
// ---------------------------------------------------------------------------
#define GA_S 12
#define GB_S 68

template<bool RELU, bool RES>
__global__ __launch_bounds__(256, 2)
void gemm_mma(const float* __restrict__ A,
              const float* __restrict__ B,
              const float* __restrict__ bias,
              const float* __restrict__ res,
              float* __restrict__ C,
              int M, int N, int K) {
    __shared__ uint2 Ap[128 * GA_S];
    __shared__ uint2 Bp[8 * GB_S];

    const int n0   = blockIdx.x * 64;
    const int m0   = blockIdx.y * 128;
    const int tid  = threadIdx.x;
    const int lane = tid & 31;
    const int warp = tid >> 5;
    const int g    = lane >> 2;
    const int tig  = lane & 3;
    const int wrow = warp * 16;

    // loader coords
    const int ar = tid >> 1, acc_ = tid & 1;               // A: row, k16 chunk
    const int bcc = tid & 15;                              // B: col chunk (4)
    const int bks = (tid >> 6) & 1, btr = (tid >> 4) & 3;  // B: k16 chunk, row-in-group

    float acc[8][4];
    #pragma unroll
    for (int i = 0; i < 8; i++)
        #pragma unroll
        for (int j = 0; j < 4; j++) acc[i][j] = 0.0f;

    for (int k0 = 0; k0 < K; k0 += 32) {
        __syncthreads();
        // A fill: row ar, cols [16*acc_, +16)
        {
            const float* src = A + (size_t)(m0 + ar) * K + k0 + acc_ * 16;
            float f[16];
            #pragma unroll
            for (int c = 0; c < 4; c++) {
                float4 v = *(const float4*)(src + c * 4);
                f[c*4+0] = v.x; f[c*4+1] = v.y; f[c*4+2] = v.z; f[c*4+3] = v.w;
            }
            uint4* d4 = (uint4*)(Ap + ar * GA_S + acc_ * 4);
            d4[0] = make_uint4(f2h2(f[0], f[1]), f2h2(f[8],  f[9]),
                               f2h2(f[2], f[3]), f2h2(f[10], f[11]));
            d4[1] = make_uint4(f2h2(f[4], f[5]), f2h2(f[12], f[13]),
                               f2h2(f[6], f[7]), f2h2(f[14], f[15]));
        }
        // B fill (threads 0-127): rows (r0,r0+1,r0+8,r0+9) x 4 cols
        if (tid < 128) {
            int r0 = bks * 16 + 2 * btr;
            const float* s0 = B + (size_t)(k0 + r0) * N + n0 + bcc * 4;
            float4 a0 = *(const float4*)s0;
            float4 a1 = *(const float4*)(s0 + (size_t)1 * N);
            float4 a2 = *(const float4*)(s0 + (size_t)8 * N);
            float4 a3 = *(const float4*)(s0 + (size_t)9 * N);
            uint4* d4 = (uint4*)(Bp + (bks * 4 + btr) * GB_S + bcc * 4);
            d4[0] = make_uint4(f2h2(a0.x, a1.x), f2h2(a2.x, a3.x),
                               f2h2(a0.y, a1.y), f2h2(a2.y, a3.y));
            d4[1] = make_uint4(f2h2(a0.z, a1.z), f2h2(a2.z, a3.z),
                               f2h2(a0.w, a1.w), f2h2(a2.w, a3.w));
        }
        __syncthreads();

        #pragma unroll
        for (int ks = 0; ks < 2; ks++) {
            uint2 aa = Ap[(wrow + g)     * GA_S + ks * 4 + tig];
            uint2 ab = Ap[(wrow + 8 + g) * GA_S + ks * 4 + tig];
            #pragma unroll
            for (int nf = 0; nf < 8; nf++) {
                uint2 bb = Bp[(ks * 4 + tig) * GB_S + nf * 8 + g];
                mma_f16(acc[nf], aa.x, ab.x, aa.y, ab.y, bb.x, bb.y);
            }
        }
    }

    const int row0 = m0 + wrow + g;
    #pragma unroll
    for (int nf = 0; nf < 8; nf++) {
        int col = n0 + nf * 8 + 2 * tig;
        float2 bi = *(const float2*)(bias + col);
        size_t idx0 = (size_t)row0 * N + col;
        size_t idx1 = idx0 + (size_t)8 * N;
        float2 va, vb;
        va.x = acc[nf][0] + bi.x; va.y = acc[nf][1] + bi.y;
        vb.x = acc[nf][2] + bi.x; vb.y = acc[nf][3] + bi.y;
        if (RELU) {
            va.x = fmaxf(va.x, 0.0f); va.y = fmaxf(va.y, 0.0f);
            vb.x = fmaxf(vb.x, 0.0f); vb.y = fmaxf(vb.y, 0.0f);
        }
        if (RES) {
            float2 ra = *(const float2*)(res + idx0);
            float2 rb = *(const float2*)(res + idx1);
            va.x += ra.x; va.y += ra.y;
            vb.x += rb.x; vb.y += rb.y;
        }
        *(float2*)(C + idx0) = va;
        *(float2*)(C + idx1) = vb;
    }
}

// ---------------------------------------------------------------------------
extern "C" void kernel_launch(void* const* d_in, const int* in_sizes, int n_in,
                              void* d_out, int out_size) {
    const float* x    = (const float*)d_in[0];
    const float* enc  = (const float*)d_in[1];
    const int*   mask = (const int*)  d_in[2];
    const float* ln1g = (const float*)d_in[3];
    const float* ln1b = (const float*)d_in[4];
    const float* ln2g = (const float*)d_in[5];
    const float* ln2b = (const float*)d_in[6];
    const float* ln3g = (const float*)d_in[7];
    const float* ln3b = (const float*)d_in[8];
    const float* W1   = (const float*)d_in[9];
    const float* b1   = (const float*)d_in[10];
    const float* W2   = (const float*)d_in[11];
    const float* b2   = (const float*)d_in[12];
    float* out = (float*)d_out;

    float *gx, *gxn, *gh;
    cudaGetSymbolAddress((void**)&gx,  g_x);
    cudaGetSymbolAddress((void**)&gxn, g_xn);
    cudaGetSymbolAddress((void**)&gh,  g_h);

    cudaFuncSetAttribute(attn_mma_kernel,
                         cudaFuncAttributeMaxDynamicSharedMemorySize,
                         ATTN_SMEM_BYTES);

    dim3 attn_grid(SEQ / BM, HEADS, BATCH);

    // 1) x1 = LN1(x); x' = x + selfattn(x1, mask)
    ln_kernel<<<NROWS, 128>>>(x, ln1g, ln1b, gxn);
    attn_mma_kernel<<<attn_grid, 256, ATTN_SMEM_BYTES>>>(gxn, gxn, mask, x, gx);

    // 2) x1 = LN2(x'); x'' = x' + crossattn(x1, enc)
    ln_kernel<<<NROWS, 128>>>(gx, ln2g, ln2b, gxn);
    attn_mma_kernel<<<attn_grid, 256, ATTN_SMEM_BYTES>>>(gxn, enc, nullptr, gx, gx);

    // 3) x1 = LN3(x''); out = x'' + relu(x1 W1 + b1) W2 + b2
    ln_kernel<<<NROWS, 128>>>(gx, ln3g, ln3b, gxn);
    gemm_mma<true,  false><<<dim3(D_FF / 64,    NROWS / 128), 256>>>(
        gxn, W1, b1, nullptr, gh, NROWS, D_FF, D_MODEL);
    gemm_mma<false, true ><<<dim3(D_MODEL / 64, NROWS / 128), 256>>>(
        gh, W2, b2, gx, out, NROWS, D_MODEL, D_FF);
}

// round 9
// speedup vs baseline: 1.5997x; 1.1037x over previous
#include <cuda_runtime.h>
#include <cuda_fp16.h>
#include <math.h>
#include <stdint.h>

#define D_MODEL 512
#define HEADS   8
#define DKH     64
#define SEQ     2048
#define BATCH   4
#define D_FF    1024
#define NROWS   (BATCH*SEQ)   // 8192

// Scratch (static device arrays — no allocation at runtime)
__device__ float    g_x [NROWS * D_MODEL];
__device__ float    g_xn[NROWS * D_MODEL];
__device__ float    g_h [NROWS * D_FF];
__device__ uint32_t g_pm[BATCH * SEQ * (SEQ / 32)];   // packed mask bits (2MB)

// ---------------------------------------------------------------------------
// fp16 helpers
// ---------------------------------------------------------------------------
__device__ __forceinline__ uint32_t f2h2(float lo, float hi) {
    __half2 h = __floats2half2_rn(lo, hi);   // .x (low 16b) = lo
    return *(uint32_t*)&h;
}

__device__ __forceinline__ void mma_f16(float c[4],
                                        uint32_t a0, uint32_t a1, uint32_t a2, uint32_t a3,
                                        uint32_t b0, uint32_t b1) {
    asm volatile(
        "mma.sync.aligned.m16n8k16.row.col.f32.f16.f16.f32 "
        "{%0,%1,%2,%3}, {%4,%5,%6,%7}, {%8,%9}, {%0,%1,%2,%3};\n"
        : "+f"(c[0]), "+f"(c[1]), "+f"(c[2]), "+f"(c[3])
        : "r"(a0), "r"(a1), "r"(a2), "r"(a3), "r"(b0), "r"(b1));
}

// ---------------------------------------------------------------------------
// Mask packing: bit j of pm[i/32] = (mask[i] != 0). 1 warp handles 1024 ints.
// ---------------------------------------------------------------------------
__device__ __forceinline__ uint32_t spread4(uint32_t x) {
    x &= 0xFFu;
    x = (x | (x << 12)) & 0x000F000Fu;
    x = (x | (x << 6))  & 0x03030303u;
    x = (x | (x << 3))  & 0x11111111u;
    return x;
}

__global__ void pack_mask_kernel(const int* __restrict__ mask,
                                 uint32_t* __restrict__ pm) {
    int w    = (blockIdx.x * blockDim.x + threadIdx.x) >> 5;
    int lane = threadIdx.x & 31;
    size_t base = (size_t)w * 1024;
    #pragma unroll
    for (int it = 0; it < 8; it++) {
        int4 v = *(const int4*)(mask + base + it * 128 + lane * 4);
        uint32_t b0 = __ballot_sync(0xffffffffu, v.x != 0);
        uint32_t b1 = __ballot_sync(0xffffffffu, v.y != 0);
        uint32_t b2 = __ballot_sync(0xffffffffu, v.z != 0);
        uint32_t b3 = __ballot_sync(0xffffffffu, v.w != 0);
        if (lane < 4) {
            uint32_t word =  spread4(b0 >> (8 * lane))
                          | (spread4(b1 >> (8 * lane)) << 1)
                          | (spread4(b2 >> (8 * lane)) << 2)
                          | (spread4(b3 >> (8 * lane)) << 3);
            pm[base / 32 + it * 4 + lane] = word;
        }
    }
}

// ---------------------------------------------------------------------------
// LayerNorm: one block per row (512 elems), 128 threads x float4
// ---------------------------------------------------------------------------
__global__ void ln_kernel(const float* __restrict__ x,
                          const float* __restrict__ gamma,
                          const float* __restrict__ beta,
                          float* __restrict__ y) {
    int row = blockIdx.x;
    int t   = threadIdx.x;
    const float4* xr = (const float4*)(x + (size_t)row * D_MODEL);
    float4 v = xr[t];
    float s  = v.x + v.y + v.z + v.w;
    float ss = v.x*v.x + v.y*v.y + v.z*v.z + v.w*v.w;
    #pragma unroll
    for (int o = 16; o > 0; o >>= 1) {
        s  += __shfl_xor_sync(0xffffffffu, s,  o);
        ss += __shfl_xor_sync(0xffffffffu, ss, o);
    }
    __shared__ float as[4], ass[4];
    int w = t >> 5;
    if ((t & 31) == 0) { as[w] = s; ass[w] = ss; }
    __syncthreads();
    s  = as[0]  + as[1]  + as[2]  + as[3];
    ss = ass[0] + ass[1] + ass[2] + ass[3];
    float mu  = s * (1.0f / D_MODEL);
    float var = ss * (1.0f / D_MODEL) - mu * mu;
    float rs  = rsqrtf(var + 1e-5f);
    float4 g4 = ((const float4*)gamma)[t];
    float4 b4 = ((const float4*)beta)[t];
    float4 o4;
    o4.x = (v.x - mu) * rs * g4.x + b4.x;
    o4.y = (v.y - mu) * rs * g4.y + b4.y;
    o4.z = (v.z - mu) * rs * g4.z + b4.z;
    o4.w = (v.w - mu) * rs * g4.w + b4.w;
    ((float4*)(y + (size_t)row * D_MODEL))[t] = o4;
}

// ---------------------------------------------------------------------------
// Flash attention, fp16 mma (m16n8k16). BM=128, 256 threads, warp tile 16x64.
// Software-pipelined K/V loads; packed-bit mask.
// ---------------------------------------------------------------------------
#define BM    128
#define QP_S  20
#define KP_S  20
#define VP_S  68
#define PP_S  20
#define ATTN_SMEM_BYTES ((128*QP_S + 64*KP_S + 16*VP_S + 128*PP_S) * 8)

__global__ __launch_bounds__(256, 2)
void attn_mma_kernel(const float* __restrict__ Q,
                     const float* __restrict__ KV,
                     const uint32_t* __restrict__ pm,   // packed mask, may be null
                     const float* __restrict__ res,
                     float* __restrict__ out) {
    extern __shared__ uint2 sm2[];
    uint2* Qp = sm2;
    uint2* Kp = Qp + 128 * QP_S;
    uint2* Vp = Kp + 64 * KP_S;
    uint2* Pp = Vp + 16 * VP_S;

    const int q0   = blockIdx.x * BM;
    const int h    = blockIdx.y;
    const int b    = blockIdx.z;
    const int tid  = threadIdx.x;
    const int lane = tid & 31;
    const int warp = tid >> 5;
    const int g    = lane >> 2;
    const int tig  = lane & 3;
    const int wrow = warp * 16;

    // ---- Stage Q [128 x 64], scaled by 1/8, packed fp16 pairs ----
    #pragma unroll
    for (int it = 0; it < 2; it++) {
        int i = tid + it * 256;
        int r = i >> 2, cc = i & 3;
        const float* src = Q + ((size_t)(b * SEQ + q0 + r)) * D_MODEL + h * DKH + cc * 16;
        float f[16];
        #pragma unroll
        for (int c = 0; c < 4; c++) {
            float4 v = *(const float4*)(src + c * 4);
            f[c*4+0] = v.x * 0.125f; f[c*4+1] = v.y * 0.125f;
            f[c*4+2] = v.z * 0.125f; f[c*4+3] = v.w * 0.125f;
        }
        uint4* d4 = (uint4*)(Qp + r * QP_S + cc * 4);
        d4[0] = make_uint4(f2h2(f[0], f[1]), f2h2(f[8],  f[9]),
                           f2h2(f[2], f[3]), f2h2(f[10], f[11]));
        d4[1] = make_uint4(f2h2(f[4], f[5]), f2h2(f[12], f[13]),
                           f2h2(f[6], f[7]), f2h2(f[14], f[15]));
    }

    float oacc[8][4];
    #pragma unroll
    for (int i = 0; i < 8; i++)
        #pragma unroll
        for (int j = 0; j < 4; j++) oacc[i][j] = 0.0f;

    float mrow[2] = {-INFINITY, -INFINITY};
    float lrow[2] = {0.0f, 0.0f};

    // loader coords
    const int kr  = tid >> 2,  kcc = tid & 3;
    const int vcc = tid & 15;
    const int vks = (tid >> 6) & 3, vtr = (tid >> 4) & 3;
    const int vr0 = vks * 16 + 2 * vtr;

    float4 kf[4], vf[4];   // prefetched raw tile

    auto ldg_tile = [&](int k0) {
        const float* ks_ = KV + ((size_t)(b * SEQ + k0 + kr)) * D_MODEL + h * DKH + kcc * 16;
        kf[0] = *(const float4*)(ks_);
        kf[1] = *(const float4*)(ks_ + 4);
        kf[2] = *(const float4*)(ks_ + 8);
        kf[3] = *(const float4*)(ks_ + 12);
        const float* vs_ = KV + ((size_t)(b * SEQ + k0 + vr0)) * D_MODEL + h * DKH + vcc * 4;
        vf[0] = *(const float4*)(vs_);
        vf[1] = *(const float4*)(vs_ + (size_t)1 * D_MODEL);
        vf[2] = *(const float4*)(vs_ + (size_t)8 * D_MODEL);
        vf[3] = *(const float4*)(vs_ + (size_t)9 * D_MODEL);
    };
    auto sts_tile = [&]() {
        uint4* dk = (uint4*)(Kp + kr * KP_S + kcc * 4);
        dk[0] = make_uint4(f2h2(kf[0].x, kf[0].y), f2h2(kf[2].x, kf[2].y),
                           f2h2(kf[0].z, kf[0].w), f2h2(kf[2].z, kf[2].w));
        dk[1] = make_uint4(f2h2(kf[1].x, kf[1].y), f2h2(kf[3].x, kf[3].y),
                           f2h2(kf[1].z, kf[1].w), f2h2(kf[3].z, kf[3].w));
        uint4* dv = (uint4*)(Vp + (vks * 4 + vtr) * VP_S + vcc * 4);
        dv[0] = make_uint4(f2h2(vf[0].x, vf[1].x), f2h2(vf[2].x, vf[3].x),
                           f2h2(vf[0].y, vf[1].y), f2h2(vf[2].y, vf[3].y));
        dv[1] = make_uint4(f2h2(vf[0].z, vf[1].z), f2h2(vf[2].z, vf[3].z),
                           f2h2(vf[0].w, vf[1].w), f2h2(vf[2].w, vf[3].w));
    };

    ldg_tile(0);

    for (int kt = 0; kt < SEQ / 64; kt++) {
        __syncthreads();   // prev compute done with Kp/Vp (Qp staged, 1st iter)
        sts_tile();
        __syncthreads();
        if (kt + 1 < SEQ / 64) ldg_tile((kt + 1) * 64);   // latency hidden by compute

        // mask bits for rows g / g+8 (broadcast within quad, L2-resident)
        uint2 pmA, pmB;
        if (pm != nullptr) {
            const uint32_t* pr = pm + ((size_t)(b * SEQ + q0 + wrow + g)) * (SEQ / 32) + kt * 2;
            pmA = *(const uint2*)pr;
            pmB = *(const uint2*)(pr + (size_t)8 * (SEQ / 32));
        }

        // ---- S = Q K^T ----
        float sacc[8][4];
        #pragma unroll
        for (int i = 0; i < 8; i++)
            #pragma unroll
            for (int j = 0; j < 4; j++) sacc[i][j] = 0.0f;

        #pragma unroll
        for (int ks = 0; ks < 4; ks++) {
            uint2 qa = Qp[(wrow + g)     * QP_S + ks * 4 + tig];
            uint2 qb = Qp[(wrow + 8 + g) * QP_S + ks * 4 + tig];
            #pragma unroll
            for (int nf = 0; nf < 8; nf++) {
                uint2 kb = Kp[(nf * 8 + g) * KP_S + ks * 4 + tig];
                mma_f16(sacc[nf], qa.x, qb.x, qa.y, qb.y, kb.x, kb.y);
            }
        }

        if (pm != nullptr) {
            #pragma unroll
            for (int nf = 0; nf < 8; nf++) {
                uint32_t wA = (nf < 4) ? pmA.x : pmA.y;
                uint32_t wB = (nf < 4) ? pmB.x : pmB.y;
                int sh = ((nf & 3) * 8) + 2 * tig;
                if (!((wA >> sh) & 1u)) sacc[nf][0] = -1e9f;
                if (!((wA >> sh) & 2u)) sacc[nf][1] = -1e9f;
                if (!((wB >> sh) & 1u)) sacc[nf][2] = -1e9f;
                if (!((wB >> sh) & 2u)) sacc[nf][3] = -1e9f;
            }
        }

        // ---- online softmax ----
        float tm0 = -INFINITY, tm1 = -INFINITY;
        #pragma unroll
        for (int nf = 0; nf < 8; nf++) {
            tm0 = fmaxf(tm0, fmaxf(sacc[nf][0], sacc[nf][1]));
            tm1 = fmaxf(tm1, fmaxf(sacc[nf][2], sacc[nf][3]));
        }
        tm0 = fmaxf(tm0, __shfl_xor_sync(0xffffffffu, tm0, 1));
        tm0 = fmaxf(tm0, __shfl_xor_sync(0xffffffffu, tm0, 2));
        tm1 = fmaxf(tm1, __shfl_xor_sync(0xffffffffu, tm1, 1));
        tm1 = fmaxf(tm1, __shfl_xor_sync(0xffffffffu, tm1, 2));

        float mn0 = fmaxf(mrow[0], tm0), mn1 = fmaxf(mrow[1], tm1);
        float c0 = __expf(mrow[0] - mn0), c1 = __expf(mrow[1] - mn1);
        float s0 = 0.0f, s1 = 0.0f;
        #pragma unroll
        for (int nf = 0; nf < 8; nf++) {
            float p0 = __expf(sacc[nf][0] - mn0);
            float p1 = __expf(sacc[nf][1] - mn0);
            float p2 = __expf(sacc[nf][2] - mn1);
            float p3 = __expf(sacc[nf][3] - mn1);
            s0 += p0 + p1; s1 += p2 + p3;
            sacc[nf][0] = p0; sacc[nf][1] = p1;
            sacc[nf][2] = p2; sacc[nf][3] = p3;
        }
        s0 += __shfl_xor_sync(0xffffffffu, s0, 1);
        s0 += __shfl_xor_sync(0xffffffffu, s0, 2);
        s1 += __shfl_xor_sync(0xffffffffu, s1, 1);
        s1 += __shfl_xor_sync(0xffffffffu, s1, 2);

        mrow[0] = mn0; mrow[1] = mn1;
        lrow[0] = lrow[0] * c0 + s0;
        lrow[1] = lrow[1] * c1 + s1;

        #pragma unroll
        for (int df = 0; df < 8; df++) {
            oacc[df][0] *= c0; oacc[df][1] *= c0;
            oacc[df][2] *= c1; oacc[df][3] *= c1;
        }

        // ---- store P as fp16 pairs (warp-private rows) ----
        #pragma unroll
        for (int ks = 0; ks < 4; ks++) {
            Pp[(wrow + g)     * PP_S + ks * 4 + tig] =
                make_uint2(f2h2(sacc[2*ks][0],   sacc[2*ks][1]),
                           f2h2(sacc[2*ks+1][0], sacc[2*ks+1][1]));
            Pp[(wrow + 8 + g) * PP_S + ks * 4 + tig] =
                make_uint2(f2h2(sacc[2*ks][2],   sacc[2*ks][3]),
                           f2h2(sacc[2*ks+1][2], sacc[2*ks+1][3]));
        }
        __syncwarp();

        // ---- O += P V ----
        #pragma unroll
        for (int ks = 0; ks < 4; ks++) {
            uint2 pa = Pp[(wrow + g)     * PP_S + ks * 4 + tig];
            uint2 pb = Pp[(wrow + 8 + g) * PP_S + ks * 4 + tig];
            #pragma unroll
            for (int df = 0; df < 8; df++) {
                uint2 vb = Vp[(ks * 4 + tig) * VP_S + df * 8 + g];
                mma_f16(oacc[df], pa.x, pb.x, pa.y, pb.y, vb.x, vb.y);
            }
        }
    }

    // ---- epilogue: normalize + residual ----
    float inv0 = 1.0f / lrow[0], inv1 = 1.0f / lrow[1];
    int r = q0 + wrow + g;
    #pragma unroll
    for (int df = 0; df < 8; df++) {
        size_t idx0 = ((size_t)(b * SEQ + r)) * D_MODEL + h * DKH + df * 8 + 2 * tig;
        size_t idx1 = idx0 + (size_t)8 * D_MODEL;
        float2 ra = *(const float2*)(res + idx0);
        float2 rb = *(const float2*)(res + idx1);
        float2 oa, ob;
        oa.x = ra.x + oacc[df][0] * inv0;
        oa.y = ra.y + oacc[df][1] * inv0;
        ob.x = rb.x + oacc[df][2] * inv1;
        ob.y = rb.y + oacc[df][3] * inv1;
        *(float2*)(out + idx0) = oa;
        *(float2*)(out + idx1) = ob;
    }
}

// ---------------------------------------------------------------------------
// fp16 mma GEMM: C[M,N] = A[M,K] @ B[K,N] + bias (+ReLU) (+res).
// Block 128x128, BK=32, 256 threads (8 warps), warp tile 16x128. Pipelined.
// ---------------------------------------------------------------------------
#define GA_S 12    // uint2 stride per A row
#define GB_S 132   // uint2 stride per B row-pair (128 + pad 4)

template<bool RELU, bool RES>
__global__ __launch_bounds__(256, 2)
void gemm_mma(const float* __restrict__ A,
              const float* __restrict__ B,
              const float* __restrict__ bias,
              const float* __restrict__ res,
              float* __restrict__ C,
              int M, int N, int K) {
    __shared__ uint2 Ap[128 * GA_S];
    __shared__ uint2 Bp[8 * GB_S];

    const int n0   = blockIdx.x * 128;
    const int m0   = blockIdx.y * 128;
    const int tid  = threadIdx.x;
    const int lane = tid & 31;
    const int warp = tid >> 5;
    const int g    = lane >> 2;
    const int tig  = lane & 3;
    const int wrow = warp * 16;

    // loader coords
    const int ar  = tid >> 1, ah = tid & 1;                 // A: row, k16 chunk
    const int bcc = tid & 31;                               // B: col chunk (4 cols)
    const int bks = (tid >> 7) & 1, btr = (tid >> 5) & 3;   // B: k16 chunk, row-in-group
    const int br0 = bks * 16 + 2 * btr;

    float4 af[4], bf[4];

    auto ldg_tiles = [&](int k0) {
        const float* as_ = A + (size_t)(m0 + ar) * K + k0 + ah * 16;
        af[0] = *(const float4*)(as_);
        af[1] = *(const float4*)(as_ + 4);
        af[2] = *(const float4*)(as_ + 8);
        af[3] = *(const float4*)(as_ + 12);
        const float* bs_ = B + (size_t)(k0 + br0) * N + n0 + bcc * 4;
        bf[0] = *(const float4*)(bs_);
        bf[1] = *(const float4*)(bs_ + (size_t)1 * N);
        bf[2] = *(const float4*)(bs_ + (size_t)8 * N);
        bf[3] = *(const float4*)(bs_ + (size_t)9 * N);
    };
    auto sts_tiles = [&]() {
        uint4* da = (uint4*)(Ap + ar * GA_S + ah * 4);
        da[0] = make_uint4(f2h2(af[0].x, af[0].y), f2h2(af[2].x, af[2].y),
                           f2h2(af[0].z, af[0].w), f2h2(af[2].z, af[2].w));
        da[1] = make_uint4(f2h2(af[1].x, af[1].y), f2h2(af[3].x, af[3].y),
                           f2h2(af[1].z, af[1].w), f2h2(af[3].z, af[3].w));
        uint4* db = (uint4*)(Bp + (bks * 4 + btr) * GB_S + bcc * 4);
        db[0] = make_uint4(f2h2(bf[0].x, bf[1].x), f2h2(bf[2].x, bf[3].x),
                           f2h2(bf[0].y, bf[1].y), f2h2(bf[2].y, bf[3].y));
        db[1] = make_uint4(f2h2(bf[0].z, bf[1].z), f2h2(bf[2].z, bf[3].z),
                           f2h2(bf[0].w, bf[1].w), f2h2(bf[2].w, bf[3].w));
    };

    float acc[16][4];
    #pragma unroll
    for (int i = 0; i < 16; i++)
        #pragma unroll
        for (int j = 0; j < 4; j++) acc[i][j] = 0.0f;

    ldg_tiles(0);

    for (int k0 = 0; k0 < K; k0 += 32) {
        __syncthreads();
        sts_tiles();
        __syncthreads();
        if (k0 + 32 < K) ldg_tiles(k0 + 32);

        #pragma unroll
        for (int ks = 0; ks < 2; ks++) {
            uint2 aa = Ap[(wrow + g)     * GA_S + ks * 4 + tig];
            uint2 ab = Ap[(wrow + 8 + g) * GA_S + ks * 4 + tig];
            #pragma unroll
            for (int nf = 0; nf < 16; nf++) {
                uint2 bb = Bp[(ks * 4 + tig) * GB_S + nf * 8 + g];
                mma_f16(acc[nf], aa.x, ab.x, aa.y, ab.y, bb.x, bb.y);
            }
        }
    }

    const int row0 = m0 + wrow + g;
    #pragma unroll
    for (int nf = 0; nf < 16; nf++) {
        int col = n0 + nf * 8 + 2 * tig;
        float2 bi = *(const float2*)(bias + col);
        size_t idx0 = (size_t)row0 * N + col;
        size_t idx1 = idx0 + (size_t)8 * N;
        float2 va, vb;
        va.x = acc[nf][0] + bi.x; va.y = acc[nf][1] + bi.y;
        vb.x = acc[nf][2] + bi.x; vb.y = acc[nf][3] + bi.y;
        if (RELU) {
            va.x = fmaxf(va.x, 0.0f); va.y = fmaxf(va.y, 0.0f);
            vb.x = fmaxf(vb.x, 0.0f); vb.y = fmaxf(vb.y, 0.0f);
        }
        if (RES) {
            float2 ra = *(const float2*)(res + idx0);
            float2 rb = *(const float2*)(res + idx1);
            va.x += ra.x; va.y += ra.y;
            vb.x += rb.x; vb.y += rb.y;
        }
        *(float2*)(C + idx0) = va;
        *(float2*)(C + idx1) = vb;
    }
}

// ---------------------------------------------------------------------------
extern "C" void kernel_launch(void* const* d_in, const int* in_sizes, int n_in,
                              void* d_out, int out_size) {
    const float* x    = (const float*)d_in[0];
    const float* enc  = (const float*)d_in[1];
    const int*   mask = (const int*)  d_in[2];
    const float* ln1g = (const float*)d_in[3];
    const float* ln1b = (const float*)d_in[4];
    const float* ln2g = (const float*)d_in[5];
    const float* ln2b = (const float*)d_in[6];
    const float* ln3g = (const float*)d_in[7];
    const float* ln3b = (const float*)d_in[8];
    const float* W1   = (const float*)d_in[9];
    const float* b1   = (const float*)d_in[10];
    const float* W2   = (const float*)d_in[11];
    const float* b2   = (const float*)d_in[12];
    float* out = (float*)d_out;

    float *gx, *gxn, *gh;
    uint32_t* gpm;
    cudaGetSymbolAddress((void**)&gx,  g_x);
    cudaGetSymbolAddress((void**)&gxn, g_xn);
    cudaGetSymbolAddress((void**)&gh,  g_h);
    cudaGetSymbolAddress((void**)&gpm, g_pm);

    cudaFuncSetAttribute(attn_mma_kernel,
                         cudaFuncAttributeMaxDynamicSharedMemorySize,
                         ATTN_SMEM_BYTES);

    dim3 attn_grid(SEQ / BM, HEADS, BATCH);

    // pack mask bits: 16M ints -> 2MB bits (1024 ints per warp)
    pack_mask_kernel<<<(BATCH * SEQ * SEQ) / 1024 / 8, 256>>>(mask, gpm);

    // 1) x1 = LN1(x); x' = x + selfattn(x1, mask)
    ln_kernel<<<NROWS, 128>>>(x, ln1g, ln1b, gxn);
    attn_mma_kernel<<<attn_grid, 256, ATTN_SMEM_BYTES>>>(gxn, gxn, gpm, x, gx);

    // 2) x1 = LN2(x'); x'' = x' + crossattn(x1, enc)
    ln_kernel<<<NROWS, 128>>>(gx, ln2g, ln2b, gxn);
    attn_mma_kernel<<<attn_grid, 256, ATTN_SMEM_BYTES>>>(gxn, enc, nullptr, gx, gx);

    // 3) x1 = LN3(x''); out = x'' + relu(x1 W1 + b1) W2 + b2
    ln_kernel<<<NROWS, 128>>>(gx, ln3g, ln3b, gxn);
    gemm_mma<true,  false><<<dim3(D_FF / 128,    NROWS / 128), 256>>>(
        gxn, W1, b1, nullptr, gh, NROWS, D_FF, D_MODEL);
    gemm_mma<false, true ><<<dim3(D_MODEL / 128, NROWS / 128), 256>>>(
        gh, W2, b2, gx, out, NROWS, D_MODEL, D_FF);
}

// round 10
// speedup vs baseline: 1.9365x; 1.2105x over previous
#include <cuda_runtime.h>
#include <cuda_fp16.h>
#include <math.h>
#include <stdint.h>

#define D_MODEL 512
#define HEADS   8
#define DKH     64
#define SEQ     2048
#define BATCH   4
#define D_FF    1024
#define NROWS   (BATCH*SEQ)   // 8192

// Scratch (static device arrays — no allocation at runtime)
__device__ float    g_x  [NROWS * D_MODEL];          // residual stream (fp32)
__device__ uint32_t g_xnh[NROWS * D_MODEL / 2];      // LN output, fp16 pairs
__device__ uint32_t g_ench[NROWS * D_MODEL / 2];     // encoder_output fp16
__device__ uint32_t g_hh [NROWS * D_FF / 2];         // FFN hidden fp16
__device__ uint32_t g_w1h[D_MODEL * D_FF / 2];       // W1 fp16
__device__ uint32_t g_w2h[D_FF * D_MODEL / 2];       // W2 fp16
__device__ uint32_t g_pm [BATCH * SEQ * (SEQ / 32)]; // packed mask bits (2MB)

// ---------------------------------------------------------------------------
// helpers
// ---------------------------------------------------------------------------
__device__ __forceinline__ uint32_t f2h2(float lo, float hi) {
    __half2 h = __floats2half2_rn(lo, hi);
    return *(uint32_t*)&h;
}
__device__ __forceinline__ uint32_t h2lo(uint32_t a, uint32_t b) {  // {a.h0,b.h0}
    return __byte_perm(a, b, 0x5410);
}
__device__ __forceinline__ uint32_t h2hi(uint32_t a, uint32_t b) {  // {a.h1,b.h1}
    return __byte_perm(a, b, 0x7632);
}

__device__ __forceinline__ void mma_f16(float c[4],
                                        uint32_t a0, uint32_t a1, uint32_t a2, uint32_t a3,
                                        uint32_t b0, uint32_t b1) {
    asm volatile(
        "mma.sync.aligned.m16n8k16.row.col.f32.f16.f16.f32 "
        "{%0,%1,%2,%3}, {%4,%5,%6,%7}, {%8,%9}, {%0,%1,%2,%3};\n"
        : "+f"(c[0]), "+f"(c[1]), "+f"(c[2]), "+f"(c[3])
        : "r"(a0), "r"(a1), "r"(a2), "r"(a3), "r"(b0), "r"(b1));
}

// ---------------------------------------------------------------------------
// fp32 -> fp16 pair converter (grid-stride, float4 -> uint2)
// ---------------------------------------------------------------------------
__global__ void cvt_h_kernel(const float* __restrict__ x,
                             uint32_t* __restrict__ yh, int n4) {
    int i = blockIdx.x * blockDim.x + threadIdx.x;
    int stride = gridDim.x * blockDim.x;
    for (; i < n4; i += stride) {
        float4 v = ((const float4*)x)[i];
        ((uint2*)yh)[i] = make_uint2(f2h2(v.x, v.y), f2h2(v.z, v.w));
    }
}

// ---------------------------------------------------------------------------
// Mask packing: bit j of pm[i/32] = (mask[i] != 0). 1 warp handles 1024 ints.
// ---------------------------------------------------------------------------
__device__ __forceinline__ uint32_t spread4(uint32_t x) {
    x &= 0xFFu;
    x = (x | (x << 12)) & 0x000F000Fu;
    x = (x | (x << 6))  & 0x03030303u;
    x = (x | (x << 3))  & 0x11111111u;
    return x;
}

__global__ void pack_mask_kernel(const int* __restrict__ mask,
                                 uint32_t* __restrict__ pm) {
    int w    = (blockIdx.x * blockDim.x + threadIdx.x) >> 5;
    int lane = threadIdx.x & 31;
    size_t base = (size_t)w * 1024;
    #pragma unroll
    for (int it = 0; it < 8; it++) {
        int4 v = *(const int4*)(mask + base + it * 128 + lane * 4);
        uint32_t b0 = __ballot_sync(0xffffffffu, v.x != 0);
        uint32_t b1 = __ballot_sync(0xffffffffu, v.y != 0);
        uint32_t b2 = __ballot_sync(0xffffffffu, v.z != 0);
        uint32_t b3 = __ballot_sync(0xffffffffu, v.w != 0);
        if (lane < 4) {
            uint32_t word =  spread4(b0 >> (8 * lane))
                          | (spread4(b1 >> (8 * lane)) << 1)
                          | (spread4(b2 >> (8 * lane)) << 2)
                          | (spread4(b3 >> (8 * lane)) << 3);
            pm[base / 32 + it * 4 + lane] = word;
        }
    }
}

// ---------------------------------------------------------------------------
// LayerNorm: one block per row, 128 threads; emits fp16 pairs (uint2/thread)
// ---------------------------------------------------------------------------
__global__ void ln_kernel(const float* __restrict__ x,
                          const float* __restrict__ gamma,
                          const float* __restrict__ beta,
                          uint32_t* __restrict__ yh) {
    int row = blockIdx.x;
    int t   = threadIdx.x;
    const float4* xr = (const float4*)(x + (size_t)row * D_MODEL);
    float4 v = xr[t];
    float s  = v.x + v.y + v.z + v.w;
    float ss = v.x*v.x + v.y*v.y + v.z*v.z + v.w*v.w;
    #pragma unroll
    for (int o = 16; o > 0; o >>= 1) {
        s  += __shfl_xor_sync(0xffffffffu, s,  o);
        ss += __shfl_xor_sync(0xffffffffu, ss, o);
    }
    __shared__ float as[4], ass[4];
    int w = t >> 5;
    if ((t & 31) == 0) { as[w] = s; ass[w] = ss; }
    __syncthreads();
    s  = as[0]  + as[1]  + as[2]  + as[3];
    ss = ass[0] + ass[1] + ass[2] + ass[3];
    float mu  = s * (1.0f / D_MODEL);
    float var = ss * (1.0f / D_MODEL) - mu * mu;
    float rs  = rsqrtf(var + 1e-5f);
    float4 g4 = ((const float4*)gamma)[t];
    float4 b4 = ((const float4*)beta)[t];
    float o0 = (v.x - mu) * rs * g4.x + b4.x;
    float o1 = (v.y - mu) * rs * g4.y + b4.y;
    float o2 = (v.z - mu) * rs * g4.z + b4.z;
    float o3 = (v.w - mu) * rs * g4.w + b4.w;
    ((uint2*)(yh + (size_t)row * (D_MODEL / 2)))[t] =
        make_uint2(f2h2(o0, o1), f2h2(o2, o3));
}

// ---------------------------------------------------------------------------
// Flash attention, fp16 mma. BM=128, 256 threads, warp tile 16x64.
// Inputs Q/KV are fp16 pairs (u32). Loaders are pure u32 gathers (+prmt for V).
// ---------------------------------------------------------------------------
#define BM    128
#define QP_S  20
#define KP_S  20
#define VP_S  68
#define PP_S  20
#define ATTN_SMEM_BYTES ((128*QP_S + 64*KP_S + 16*VP_S + 128*PP_S) * 8)
#define ROWU  (D_MODEL / 2)   // u32 per row (256)

__global__ __launch_bounds__(256, 2)
void attn_mma_kernel(const uint32_t* __restrict__ Qh,
                     const uint32_t* __restrict__ KVh,
                     const uint32_t* __restrict__ pm,   // packed mask, may be null
                     const float* __restrict__ res,
                     float* __restrict__ out) {
    extern __shared__ uint2 sm2[];
    uint2* Qp = sm2;
    uint2* Kp = Qp + 128 * QP_S;
    uint2* Vp = Kp + 64 * KP_S;
    uint2* Pp = Vp + 16 * VP_S;

    const int q0   = blockIdx.x * BM;
    const int h    = blockIdx.y;
    const int b    = blockIdx.z;
    const int tid  = threadIdx.x;
    const int lane = tid & 31;
    const int warp = tid >> 5;
    const int g    = lane >> 2;
    const int tig  = lane & 3;
    const int wrow = warp * 16;

    const __half2 qscale = __float2half2_rn(0.125f);   // exact (power of 2)

    // ---- Stage Q [128 x 64], scaled by 1/8: pure gather of fp16 pairs ----
    #pragma unroll
    for (int it = 0; it < 2; it++) {
        int i = tid + it * 256;
        int r = i >> 2, cc = i & 3;
        const uint32_t* src = Qh + (size_t)(b * SEQ + q0 + r) * ROWU + h * 32 + cc * 8;
        uint4 u0 = *(const uint4*)src;
        uint4 u1 = *(const uint4*)(src + 4);
        uint32_t u[8] = {u0.x, u0.y, u0.z, u0.w, u1.x, u1.y, u1.z, u1.w};
        #pragma unroll
        for (int k = 0; k < 8; k++) {
            __half2 hv = __hmul2(*(__half2*)&u[k], qscale);
            u[k] = *(uint32_t*)&hv;
        }
        uint4* d4 = (uint4*)(Qp + r * QP_S + cc * 4);
        d4[0] = make_uint4(u[0], u[4], u[1], u[5]);
        d4[1] = make_uint4(u[2], u[6], u[3], u[7]);
    }

    float oacc[8][4];
    #pragma unroll
    for (int i = 0; i < 8; i++)
        #pragma unroll
        for (int j = 0; j < 4; j++) oacc[i][j] = 0.0f;

    float mrow[2] = {-INFINITY, -INFINITY};
    float lrow[2] = {0.0f, 0.0f};

    // loader coords
    const int kr  = tid >> 2,  kcc = tid & 3;              // K: row, k16 chunk
    const int vcc = tid & 15;                              // V: col chunk (4 cols)
    const int vks = (tid >> 6) & 3, vtr = (tid >> 4) & 3;  // V: k16 chunk, row-in-group
    const int vr0 = vks * 16 + 2 * vtr;

    uint4 kf[2];          // K prefetch: 8 u32
    uint2 vf[4];          // V prefetch: rows r0, r0+1, r0+8, r0+9 x 2 u32

    auto ldg_tile = [&](int k0) {
        const uint32_t* ks_ = KVh + (size_t)(b * SEQ + k0 + kr) * ROWU + h * 32 + kcc * 8;
        kf[0] = *(const uint4*)ks_;
        kf[1] = *(const uint4*)(ks_ + 4);
        const uint32_t* vs_ = KVh + (size_t)(b * SEQ + k0 + vr0) * ROWU + h * 32 + vcc * 2;
        vf[0] = *(const uint2*)vs_;
        vf[1] = *(const uint2*)(vs_ + (size_t)1 * ROWU);
        vf[2] = *(const uint2*)(vs_ + (size_t)8 * ROWU);
        vf[3] = *(const uint2*)(vs_ + (size_t)9 * ROWU);
    };
    auto sts_tile = [&]() {
        uint4* dk = (uint4*)(Kp + kr * KP_S + kcc * 4);
        dk[0] = make_uint4(kf[0].x, kf[1].x, kf[0].y, kf[1].y);
        dk[1] = make_uint4(kf[0].z, kf[1].z, kf[0].w, kf[1].w);
        uint4* dv = (uint4*)(Vp + (vks * 4 + vtr) * VP_S + vcc * 4);
        // cols 4vcc..+3: cross-row half pairs via prmt
        dv[0] = make_uint4(h2lo(vf[0].x, vf[1].x), h2lo(vf[2].x, vf[3].x),
                           h2hi(vf[0].x, vf[1].x), h2hi(vf[2].x, vf[3].x));
        dv[1] = make_uint4(h2lo(vf[0].y, vf[1].y), h2lo(vf[2].y, vf[3].y),
                           h2hi(vf[0].y, vf[1].y), h2hi(vf[2].y, vf[3].y));
    };

    ldg_tile(0);

    for (int kt = 0; kt < SEQ / 64; kt++) {
        __syncthreads();
        sts_tile();
        __syncthreads();
        if (kt + 1 < SEQ / 64) ldg_tile((kt + 1) * 64);

        uint2 pmA, pmB;
        if (pm != nullptr) {
            const uint32_t* pr = pm + ((size_t)(b * SEQ + q0 + wrow + g)) * (SEQ / 32) + kt * 2;
            pmA = *(const uint2*)pr;
            pmB = *(const uint2*)(pr + (size_t)8 * (SEQ / 32));
        }

        // ---- S = Q K^T ----
        float sacc[8][4];
        #pragma unroll
        for (int i = 0; i < 8; i++)
            #pragma unroll
            for (int j = 0; j < 4; j++) sacc[i][j] = 0.0f;

        #pragma unroll
        for (int ks = 0; ks < 4; ks++) {
            uint2 qa = Qp[(wrow + g)     * QP_S + ks * 4 + tig];
            uint2 qb = Qp[(wrow + 8 + g) * QP_S + ks * 4 + tig];
            #pragma unroll
            for (int nf = 0; nf < 8; nf++) {
                uint2 kb = Kp[(nf * 8 + g) * KP_S + ks * 4 + tig];
                mma_f16(sacc[nf], qa.x, qb.x, qa.y, qb.y, kb.x, kb.y);
            }
        }

        if (pm != nullptr) {
            #pragma unroll
            for (int nf = 0; nf < 8; nf++) {
                uint32_t wA = (nf < 4) ? pmA.x : pmA.y;
                uint32_t wB = (nf < 4) ? pmB.x : pmB.y;
                int sh = ((nf & 3) * 8) + 2 * tig;
                if (!((wA >> sh) & 1u)) sacc[nf][0] = -1e9f;
                if (!((wA >> sh) & 2u)) sacc[nf][1] = -1e9f;
                if (!((wB >> sh) & 1u)) sacc[nf][2] = -1e9f;
                if (!((wB >> sh) & 2u)) sacc[nf][3] = -1e9f;
            }
        }

        // ---- online softmax ----
        float tm0 = -INFINITY, tm1 = -INFINITY;
        #pragma unroll
        for (int nf = 0; nf < 8; nf++) {
            tm0 = fmaxf(tm0, fmaxf(sacc[nf][0], sacc[nf][1]));
            tm1 = fmaxf(tm1, fmaxf(sacc[nf][2], sacc[nf][3]));
        }
        tm0 = fmaxf(tm0, __shfl_xor_sync(0xffffffffu, tm0, 1));
        tm0 = fmaxf(tm0, __shfl_xor_sync(0xffffffffu, tm0, 2));
        tm1 = fmaxf(tm1, __shfl_xor_sync(0xffffffffu, tm1, 1));
        tm1 = fmaxf(tm1, __shfl_xor_sync(0xffffffffu, tm1, 2));

        float mn0 = fmaxf(mrow[0], tm0), mn1 = fmaxf(mrow[1], tm1);
        float c0 = __expf(mrow[0] - mn0), c1 = __expf(mrow[1] - mn1);
        float s0 = 0.0f, s1 = 0.0f;
        #pragma unroll
        for (int nf = 0; nf < 8; nf++) {
            float p0 = __expf(sacc[nf][0] - mn0);
            float p1 = __expf(sacc[nf][1] - mn0);
            float p2 = __expf(sacc[nf][2] - mn1);
            float p3 = __expf(sacc[nf][3] - mn1);
            s0 += p0 + p1; s1 += p2 + p3;
            sacc[nf][0] = p0; sacc[nf][1] = p1;
            sacc[nf][2] = p2; sacc[nf][3] = p3;
        }
        s0 += __shfl_xor_sync(0xffffffffu, s0, 1);
        s0 += __shfl_xor_sync(0xffffffffu, s0, 2);
        s1 += __shfl_xor_sync(0xffffffffu, s1, 1);
        s1 += __shfl_xor_sync(0xffffffffu, s1, 2);

        mrow[0] = mn0; mrow[1] = mn1;
        lrow[0] = lrow[0] * c0 + s0;
        lrow[1] = lrow[1] * c1 + s1;

        #pragma unroll
        for (int df = 0; df < 8; df++) {
            oacc[df][0] *= c0; oacc[df][1] *= c0;
            oacc[df][2] *= c1; oacc[df][3] *= c1;
        }

        // ---- store P as fp16 pairs (warp-private rows) ----
        #pragma unroll
        for (int ks = 0; ks < 4; ks++) {
            Pp[(wrow + g)     * PP_S + ks * 4 + tig] =
                make_uint2(f2h2(sacc[2*ks][0],   sacc[2*ks][1]),
                           f2h2(sacc[2*ks+1][0], sacc[2*ks+1][1]));
            Pp[(wrow + 8 + g) * PP_S + ks * 4 + tig] =
                make_uint2(f2h2(sacc[2*ks][2],   sacc[2*ks][3]),
                           f2h2(sacc[2*ks+1][2], sacc[2*ks+1][3]));
        }
        __syncwarp();

        // ---- O += P V ----
        #pragma unroll
        for (int ks = 0; ks < 4; ks++) {
            uint2 pa = Pp[(wrow + g)     * PP_S + ks * 4 + tig];
            uint2 pb = Pp[(wrow + 8 + g) * PP_S + ks * 4 + tig];
            #pragma unroll
            for (int df = 0; df < 8; df++) {
                uint2 vb = Vp[(ks * 4 + tig) * VP_S + df * 8 + g];
                mma_f16(oacc[df], pa.x, pb.x, pa.y, pb.y, vb.x, vb.y);
            }
        }
    }

    // ---- epilogue: normalize + residual ----
    float inv0 = 1.0f / lrow[0], inv1 = 1.0f / lrow[1];
    int r = q0 + wrow + g;
    #pragma unroll
    for (int df = 0; df < 8; df++) {
        size_t idx0 = ((size_t)(b * SEQ + r)) * D_MODEL + h * DKH + df * 8 + 2 * tig;
        size_t idx1 = idx0 + (size_t)8 * D_MODEL;
        float2 ra = *(const float2*)(res + idx0);
        float2 rb = *(const float2*)(res + idx1);
        float2 oa, ob;
        oa.x = ra.x + oacc[df][0] * inv0;
        oa.y = ra.y + oacc[df][1] * inv0;
        ob.x = rb.x + oacc[df][2] * inv1;
        ob.y = rb.y + oacc[df][3] * inv1;
        *(float2*)(out + idx0) = oa;
        *(float2*)(out + idx1) = ob;
    }
}

// ---------------------------------------------------------------------------
// fp16 mma GEMM, fp16 inputs: C = A @ B + bias (+ReLU), out fp32 or fp16.
// Block 128x128, BK=32, 256 threads, warp tile 16x128. Pipelined.
// ---------------------------------------------------------------------------
#define GA_S 12
#define GB_S 132

template<bool RELU, bool RES, bool HOUT>
__global__ __launch_bounds__(256, 2)
void gemm_mma(const uint32_t* __restrict__ A,   // fp16 pairs, [M][K/2]
              const uint32_t* __restrict__ B,   // fp16 pairs, [K][N/2]
              const float* __restrict__ bias,
              const float* __restrict__ res,
              void* __restrict__ Cv,
              int M, int N, int K) {
    __shared__ uint2 Ap[128 * GA_S];
    __shared__ uint2 Bp[8 * GB_S];

    const int n0   = blockIdx.x * 128;
    const int m0   = blockIdx.y * 128;
    const int tid  = threadIdx.x;
    const int lane = tid & 31;
    const int warp = tid >> 5;
    const int g    = lane >> 2;
    const int tig  = lane & 3;
    const int wrow = warp * 16;
    const int KU   = K / 2, NU = N / 2;

    const int ar  = tid >> 1, ah = tid & 1;
    const int bcc = tid & 31;
    const int bks = (tid >> 7) & 1, btr = (tid >> 5) & 3;
    const int br0 = bks * 16 + 2 * btr;

    uint4 af[2];
    uint2 bf[4];

    auto ldg_tiles = [&](int k0) {
        const uint32_t* as_ = A + (size_t)(m0 + ar) * KU + k0 / 2 + ah * 8;
        af[0] = *(const uint4*)as_;
        af[1] = *(const uint4*)(as_ + 4);
        const uint32_t* bs_ = B + (size_t)(k0 + br0) * NU + n0 / 2 + bcc * 2;
        bf[0] = *(const uint2*)bs_;
        bf[1] = *(const uint2*)(bs_ + (size_t)1 * NU);
        bf[2] = *(const uint2*)(bs_ + (size_t)8 * NU);
        bf[3] = *(const uint2*)(bs_ + (size_t)9 * NU);
    };
    auto sts_tiles = [&]() {
        uint4* da = (uint4*)(Ap + ar * GA_S + ah * 4);
        da[0] = make_uint4(af[0].x, af[1].x, af[0].y, af[1].y);
        da[1] = make_uint4(af[0].z, af[1].z, af[0].w, af[1].w);
        uint4* db = (uint4*)(Bp + (bks * 4 + btr) * GB_S + bcc * 4);
        db[0] = make_uint4(h2lo(bf[0].x, bf[1].x), h2lo(bf[2].x, bf[3].x),
                           h2hi(bf[0].x, bf[1].x), h2hi(bf[2].x, bf[3].x));
        db[1] = make_uint4(h2lo(bf[0].y, bf[1].y), h2lo(bf[2].y, bf[3].y),
                           h2hi(bf[0].y, bf[1].y), h2hi(bf[2].y, bf[3].y));
    };

    float acc[16][4];
    #pragma unroll
    for (int i = 0; i < 16; i++)
        #pragma unroll
        for (int j = 0; j < 4; j++) acc[i][j] = 0.0f;

    ldg_tiles(0);

    for (int k0 = 0; k0 < K; k0 += 32) {
        __syncthreads();
        sts_tiles();
        __syncthreads();
        if (k0 + 32 < K) ldg_tiles(k0 + 32);

        #pragma unroll
        for (int ks = 0; ks < 2; ks++) {
            uint2 aa = Ap[(wrow + g)     * GA_S + ks * 4 + tig];
            uint2 ab = Ap[(wrow + 8 + g) * GA_S + ks * 4 + tig];
            #pragma unroll
            for (int nf = 0; nf < 16; nf++) {
                uint2 bb = Bp[(ks * 4 + tig) * GB_S + nf * 8 + g];
                mma_f16(acc[nf], aa.x, ab.x, aa.y, ab.y, bb.x, bb.y);
            }
        }
    }

    const int row0 = m0 + wrow + g;
    #pragma unroll
    for (int nf = 0; nf < 16; nf++) {
        int col = n0 + nf * 8 + 2 * tig;
        float2 bi = *(const float2*)(bias + col);
        float2 va, vb;
        va.x = acc[nf][0] + bi.x; va.y = acc[nf][1] + bi.y;
        vb.x = acc[nf][2] + bi.x; vb.y = acc[nf][3] + bi.y;
        if (RELU) {
            va.x = fmaxf(va.x, 0.0f); va.y = fmaxf(va.y, 0.0f);
            vb.x = fmaxf(vb.x, 0.0f); vb.y = fmaxf(vb.y, 0.0f);
        }
        if (HOUT) {
            uint32_t* C = (uint32_t*)Cv;
            C[((size_t)row0 * N + col) / 2]       = f2h2(va.x, va.y);
            C[((size_t)(row0 + 8) * N + col) / 2] = f2h2(vb.x, vb.y);
        } else {
            float* C = (float*)Cv;
            size_t idx0 = (size_t)row0 * N + col;
            size_t idx1 = idx0 + (size_t)8 * N;
            if (RES) {
                float2 ra = *(const float2*)(res + idx0);
                float2 rb = *(const float2*)(res + idx1);
                va.x += ra.x; va.y += ra.y;
                vb.x += rb.x; vb.y += rb.y;
            }
            *(float2*)(C + idx0) = va;
            *(float2*)(C + idx1) = vb;
        }
    }
}

// ---------------------------------------------------------------------------
extern "C" void kernel_launch(void* const* d_in, const int* in_sizes, int n_in,
                              void* d_out, int out_size) {
    const float* x    = (const float*)d_in[0];
    const float* enc  = (const float*)d_in[1];
    const int*   mask = (const int*)  d_in[2];
    const float* ln1g = (const float*)d_in[3];
    const float* ln1b = (const float*)d_in[4];
    const float* ln2g = (const float*)d_in[5];
    const float* ln2b = (const float*)d_in[6];
    const float* ln3g = (const float*)d_in[7];
    const float* ln3b = (const float*)d_in[8];
    const float* W1   = (const float*)d_in[9];
    const float* b1   = (const float*)d_in[10];
    const float* W2   = (const float*)d_in[11];
    const float* b2   = (const float*)d_in[12];
    float* out = (float*)d_out;

    float *gx;
    uint32_t *gxnh, *gench, *ghh, *gw1h, *gw2h, *gpm;
    cudaGetSymbolAddress((void**)&gx,    g_x);
    cudaGetSymbolAddress((void**)&gxnh,  g_xnh);
    cudaGetSymbolAddress((void**)&gench, g_ench);
    cudaGetSymbolAddress((void**)&ghh,   g_hh);
    cudaGetSymbolAddress((void**)&gw1h,  g_w1h);
    cudaGetSymbolAddress((void**)&gw2h,  g_w2h);
    cudaGetSymbolAddress((void**)&gpm,   g_pm);

    cudaFuncSetAttribute(attn_mma_kernel,
                         cudaFuncAttributeMaxDynamicSharedMemorySize,
                         ATTN_SMEM_BYTES);

    dim3 attn_grid(SEQ / BM, HEADS, BATCH);

    // one-time conversions (per launch)
    pack_mask_kernel<<<(BATCH * SEQ * SEQ) / 1024 / 8, 256>>>(mask, gpm);
    cvt_h_kernel<<<2048, 256>>>(enc, gench, NROWS * D_MODEL / 4);
    cvt_h_kernel<<<512,  256>>>(W1,  gw1h,  D_MODEL * D_FF / 4);
    cvt_h_kernel<<<512,  256>>>(W2,  gw2h,  D_FF * D_MODEL / 4);

    // 1) x1 = LN1(x); x' = x + selfattn(x1, mask)
    ln_kernel<<<NROWS, 128>>>(x, ln1g, ln1b, gxnh);
    attn_mma_kernel<<<attn_grid, 256, ATTN_SMEM_BYTES>>>(gxnh, gxnh, gpm, x, gx);

    // 2) x1 = LN2(x'); x'' = x' + crossattn(x1, enc)
    ln_kernel<<<NROWS, 128>>>(gx, ln2g, ln2b, gxnh);
    attn_mma_kernel<<<attn_grid, 256, ATTN_SMEM_BYTES>>>(gxnh, gench, nullptr, gx, gx);

    // 3) x1 = LN3(x''); out = x'' + relu(x1 W1 + b1) W2 + b2
    ln_kernel<<<NROWS, 128>>>(gx, ln3g, ln3b, gxnh);
    gemm_mma<true,  false, true ><<<dim3(D_FF / 128,    NROWS / 128), 256>>>(
        gxnh, gw1h, b1, nullptr, ghh, NROWS, D_FF, D_MODEL);
    gemm_mma<false, true,  false><<<dim3(D_MODEL / 128, NROWS / 128), 256>>>(
        ghh, gw2h, b2, gx, out, NROWS, D_MODEL, D_FF);
}

// round 11
// speedup vs baseline: 2.2540x; 1.1640x over previous
#include <cuda_runtime.h>
#include <cuda_fp16.h>
#include <math.h>
#include <stdint.h>

#define D_MODEL 512
#define HEADS   8
#define DKH     64
#define SEQ     2048
#define BATCH   4
#define D_FF    1024
#define NROWS   (BATCH*SEQ)   // 8192

// Scratch (static device arrays — no allocation at runtime)
__device__ float    g_x  [NROWS * D_MODEL];          // residual stream (fp32)
__device__ uint32_t g_xnh[NROWS * D_MODEL / 2];      // LN output, fp16 pairs
__device__ uint32_t g_ench[NROWS * D_MODEL / 2];     // encoder_output fp16
__device__ uint32_t g_hh [NROWS * D_FF / 2];         // FFN hidden fp16
__device__ uint32_t g_w1h[D_MODEL * D_FF / 2];       // W1 fp16
__device__ uint32_t g_w2h[D_FF * D_MODEL / 2];       // W2 fp16
__device__ uint32_t g_pm [BATCH * SEQ * (SEQ / 32)]; // packed mask bits (2MB)

// ---------------------------------------------------------------------------
// helpers
// ---------------------------------------------------------------------------
__device__ __forceinline__ uint32_t f2h2(float lo, float hi) {
    __half2 h = __floats2half2_rn(lo, hi);
    return *(uint32_t*)&h;
}
__device__ __forceinline__ uint32_t h2lo(uint32_t a, uint32_t b) {  // {a.h0,b.h0}
    return __byte_perm(a, b, 0x5410);
}
__device__ __forceinline__ uint32_t h2hi(uint32_t a, uint32_t b) {  // {a.h1,b.h1}
    return __byte_perm(a, b, 0x7632);
}
__device__ __forceinline__ uint32_t hex2(uint32_t t) {   // 2^t per fp16 lane
    uint32_t r;
    asm("ex2.approx.f16x2 %0, %1;" : "=r"(r) : "r"(t));
    return r;
}

__device__ __forceinline__ void mma_f16(float c[4],
                                        uint32_t a0, uint32_t a1, uint32_t a2, uint32_t a3,
                                        uint32_t b0, uint32_t b1) {
    asm volatile(
        "mma.sync.aligned.m16n8k16.row.col.f32.f16.f16.f32 "
        "{%0,%1,%2,%3}, {%4,%5,%6,%7}, {%8,%9}, {%0,%1,%2,%3};\n"
        : "+f"(c[0]), "+f"(c[1]), "+f"(c[2]), "+f"(c[3])
        : "r"(a0), "r"(a1), "r"(a2), "r"(a3), "r"(b0), "r"(b1));
}

#define L2E 1.4426950408889634f
#define ONE2 0x3C003C00u   // fp16 {1.0, 1.0}

// ---------------------------------------------------------------------------
// fp32 -> fp16 pair converter (grid-stride, float4 -> uint2)
// ---------------------------------------------------------------------------
__global__ void cvt_h_kernel(const float* __restrict__ x,
                             uint32_t* __restrict__ yh, int n4) {
    int i = blockIdx.x * blockDim.x + threadIdx.x;
    int stride = gridDim.x * blockDim.x;
    for (; i < n4; i += stride) {
        float4 v = ((const float4*)x)[i];
        ((uint2*)yh)[i] = make_uint2(f2h2(v.x, v.y), f2h2(v.z, v.w));
    }
}

// ---------------------------------------------------------------------------
// Mask packing: bit j of pm[i/32] = (mask[i] != 0). 1 warp handles 1024 ints.
// ---------------------------------------------------------------------------
__device__ __forceinline__ uint32_t spread4(uint32_t x) {
    x &= 0xFFu;
    x = (x | (x << 12)) & 0x000F000Fu;
    x = (x | (x << 6))  & 0x03030303u;
    x = (x | (x << 3))  & 0x11111111u;
    return x;
}

__global__ void pack_mask_kernel(const int* __restrict__ mask,
                                 uint32_t* __restrict__ pm) {
    int w    = (blockIdx.x * blockDim.x + threadIdx.x) >> 5;
    int lane = threadIdx.x & 31;
    size_t base = (size_t)w * 1024;
    #pragma unroll
    for (int it = 0; it < 8; it++) {
        int4 v = *(const int4*)(mask + base + it * 128 + lane * 4);
        uint32_t b0 = __ballot_sync(0xffffffffu, v.x != 0);
        uint32_t b1 = __ballot_sync(0xffffffffu, v.y != 0);
        uint32_t b2 = __ballot_sync(0xffffffffu, v.z != 0);
        uint32_t b3 = __ballot_sync(0xffffffffu, v.w != 0);
        if (lane < 4) {
            uint32_t word =  spread4(b0 >> (8 * lane))
                          | (spread4(b1 >> (8 * lane)) << 1)
                          | (spread4(b2 >> (8 * lane)) << 2)
                          | (spread4(b3 >> (8 * lane)) << 3);
            pm[base / 32 + it * 4 + lane] = word;
        }
    }
}

// ---------------------------------------------------------------------------
// LayerNorm: one block per row, 128 threads; emits fp16 pairs (uint2/thread)
// ---------------------------------------------------------------------------
__global__ void ln_kernel(const float* __restrict__ x,
                          const float* __restrict__ gamma,
                          const float* __restrict__ beta,
                          uint32_t* __restrict__ yh) {
    int row = blockIdx.x;
    int t   = threadIdx.x;
    const float4* xr = (const float4*)(x + (size_t)row * D_MODEL);
    float4 v = xr[t];
    float s  = v.x + v.y + v.z + v.w;
    float ss = v.x*v.x + v.y*v.y + v.z*v.z + v.w*v.w;
    #pragma unroll
    for (int o = 16; o > 0; o >>= 1) {
        s  += __shfl_xor_sync(0xffffffffu, s,  o);
        ss += __shfl_xor_sync(0xffffffffu, ss, o);
    }
    __shared__ float as[4], ass[4];
    int w = t >> 5;
    if ((t & 31) == 0) { as[w] = s; ass[w] = ss; }
    __syncthreads();
    s  = as[0]  + as[1]  + as[2]  + as[3];
    ss = ass[0] + ass[1] + ass[2] + ass[3];
    float mu  = s * (1.0f / D_MODEL);
    float var = ss * (1.0f / D_MODEL) - mu * mu;
    float rs  = rsqrtf(var + 1e-5f);
    float4 g4 = ((const float4*)gamma)[t];
    float4 b4 = ((const float4*)beta)[t];
    float o0 = (v.x - mu) * rs * g4.x + b4.x;
    float o1 = (v.y - mu) * rs * g4.y + b4.y;
    float o2 = (v.z - mu) * rs * g4.z + b4.z;
    float o3 = (v.w - mu) * rs * g4.w + b4.w;
    ((uint2*)(yh + (size_t)row * (D_MODEL / 2)))[t] =
        make_uint2(f2h2(o0, o1), f2h2(o2, o3));
}

// ---------------------------------------------------------------------------
// Flash attention, fp16 mma. BM=128, 256 threads, warp tile 16x64.
// Register-resident P (S-accum == PV A-fragment), ex2.f16x2 softmax,
// row-sum via ones-mma, double-buffered K/V (1 barrier/tile).
// ---------------------------------------------------------------------------
#define BM    128
#define QP_S  20
#define KP_S  20
#define VP_S  68
#define KSTG  (64*KP_S + 16*VP_S)    // uint2 per K/V stage
#define ATTN_SMEM_BYTES ((128*QP_S + 2*KSTG) * 8)
#define ROWU  (D_MODEL / 2)          // u32 per row (256)

__global__ __launch_bounds__(256, 2)
void attn_mma_kernel(const uint32_t* __restrict__ Qh,
                     const uint32_t* __restrict__ KVh,
                     const uint32_t* __restrict__ pm,   // packed mask, may be null
                     const float* __restrict__ res,
                     float* __restrict__ out) {
    extern __shared__ uint2 sm2[];
    uint2* Qp     = sm2;
    uint2* KVbase = Qp + 128 * QP_S;

    const int q0   = blockIdx.x * BM;
    const int h    = blockIdx.y;
    const int b    = blockIdx.z;
    const int tid  = threadIdx.x;
    const int lane = tid & 31;
    const int warp = tid >> 5;
    const int g    = lane >> 2;
    const int tig  = lane & 3;
    const int wrow = warp * 16;

    const __half2 qscale = __float2half2_rn(0.125f);   // exact (power of 2)

    // ---- Stage Q [128 x 64], scaled by 1/8: pure gather of fp16 pairs ----
    #pragma unroll
    for (int it = 0; it < 2; it++) {
        int i = tid + it * 256;
        int r = i >> 2, cc = i & 3;
        const uint32_t* src = Qh + (size_t)(b * SEQ + q0 + r) * ROWU + h * 32 + cc * 8;
        uint4 u0 = *(const uint4*)src;
        uint4 u1 = *(const uint4*)(src + 4);
        uint32_t u[8] = {u0.x, u0.y, u0.z, u0.w, u1.x, u1.y, u1.z, u1.w};
        #pragma unroll
        for (int k = 0; k < 8; k++) {
            __half2 hv = __hmul2(*(__half2*)&u[k], qscale);
            u[k] = *(uint32_t*)&hv;
        }
        uint4* d4 = (uint4*)(Qp + r * QP_S + cc * 4);
        d4[0] = make_uint4(u[0], u[4], u[1], u[5]);
        d4[1] = make_uint4(u[2], u[6], u[3], u[7]);
    }

    float oacc[8][4];
    #pragma unroll
    for (int i = 0; i < 8; i++)
        #pragma unroll
        for (int j = 0; j < 4; j++) oacc[i][j] = 0.0f;
    float sumacc[4] = {0.0f, 0.0f, 0.0f, 0.0f};

    float mrow[2] = {-INFINITY, -INFINITY};

    // loader coords
    const int kr  = tid >> 2,  kcc = tid & 3;              // K: row, k16 chunk
    const int vcc = tid & 15;                              // V: col chunk (2 u32)
    const int vks = (tid >> 6) & 3, vtr = (tid >> 4) & 3;  // V: k16 chunk, row-in-group
    const int vr0 = vks * 16 + 2 * vtr;

    uint4 kf[2];
    uint2 vf[4];

    auto ldg_tile = [&](int k0) {
        const uint32_t* ks_ = KVh + (size_t)(b * SEQ + k0 + kr) * ROWU + h * 32 + kcc * 8;
        kf[0] = *(const uint4*)ks_;
        kf[1] = *(const uint4*)(ks_ + 4);
        const uint32_t* vs_ = KVh + (size_t)(b * SEQ + k0 + vr0) * ROWU + h * 32 + vcc * 2;
        vf[0] = *(const uint2*)vs_;
        vf[1] = *(const uint2*)(vs_ + (size_t)1 * ROWU);
        vf[2] = *(const uint2*)(vs_ + (size_t)8 * ROWU);
        vf[3] = *(const uint2*)(vs_ + (size_t)9 * ROWU);
    };
    auto sts_tile = [&](uint2* Kp, uint2* Vp) {
        uint4* dk = (uint4*)(Kp + kr * KP_S + kcc * 4);
        dk[0] = make_uint4(kf[0].x, kf[1].x, kf[0].y, kf[1].y);
        dk[1] = make_uint4(kf[0].z, kf[1].z, kf[0].w, kf[1].w);
        uint4* dv = (uint4*)(Vp + (vks * 4 + vtr) * VP_S + vcc * 4);
        dv[0] = make_uint4(h2lo(vf[0].x, vf[1].x), h2lo(vf[2].x, vf[3].x),
                           h2hi(vf[0].x, vf[1].x), h2hi(vf[2].x, vf[3].x));
        dv[1] = make_uint4(h2lo(vf[0].y, vf[1].y), h2lo(vf[2].y, vf[3].y),
                           h2hi(vf[0].y, vf[1].y), h2hi(vf[2].y, vf[3].y));
    };

    ldg_tile(0);

    for (int kt = 0; kt < SEQ / 64; kt++) {
        uint2* Kp = KVbase + (kt & 1) * KSTG;
        uint2* Vp = Kp + 64 * KP_S;
        sts_tile(Kp, Vp);
        __syncthreads();   // stage ready; also covers Q staging on kt=0
        if (kt + 1 < SEQ / 64) ldg_tile((kt + 1) * 64);

        uint2 pmA, pmB;
        if (pm != nullptr) {
            const uint32_t* pr = pm + ((size_t)(b * SEQ + q0 + wrow + g)) * (SEQ / 32) + kt * 2;
            pmA = *(const uint2*)pr;
            pmB = *(const uint2*)(pr + (size_t)8 * (SEQ / 32));
        }

        // ---- S = Q K^T ----
        float sacc[8][4];
        #pragma unroll
        for (int i = 0; i < 8; i++)
            #pragma unroll
            for (int j = 0; j < 4; j++) sacc[i][j] = 0.0f;

        #pragma unroll
        for (int ks = 0; ks < 4; ks++) {
            uint2 qa = Qp[(wrow + g)     * QP_S + ks * 4 + tig];
            uint2 qb = Qp[(wrow + 8 + g) * QP_S + ks * 4 + tig];
            #pragma unroll
            for (int nf = 0; nf < 8; nf++) {
                uint2 kb = Kp[(nf * 8 + g) * KP_S + ks * 4 + tig];
                mma_f16(sacc[nf], qa.x, qb.x, qa.y, qb.y, kb.x, kb.y);
            }
        }

        if (pm != nullptr) {
            #pragma unroll
            for (int nf = 0; nf < 8; nf++) {
                uint32_t wA = (nf < 4) ? pmA.x : pmA.y;
                uint32_t wB = (nf < 4) ? pmB.x : pmB.y;
                int sh = ((nf & 3) * 8) + 2 * tig;
                if (!((wA >> sh) & 1u)) sacc[nf][0] = -1e9f;
                if (!((wA >> sh) & 2u)) sacc[nf][1] = -1e9f;
                if (!((wB >> sh) & 1u)) sacc[nf][2] = -1e9f;
                if (!((wB >> sh) & 2u)) sacc[nf][3] = -1e9f;
            }
        }

        // ---- online softmax (max only; sum comes from ones-mma) ----
        float tm0 = -INFINITY, tm1 = -INFINITY;
        #pragma unroll
        for (int nf = 0; nf < 8; nf++) {
            tm0 = fmaxf(tm0, fmaxf(sacc[nf][0], sacc[nf][1]));
            tm1 = fmaxf(tm1, fmaxf(sacc[nf][2], sacc[nf][3]));
        }
        tm0 = fmaxf(tm0, __shfl_xor_sync(0xffffffffu, tm0, 1));
        tm0 = fmaxf(tm0, __shfl_xor_sync(0xffffffffu, tm0, 2));
        tm1 = fmaxf(tm1, __shfl_xor_sync(0xffffffffu, tm1, 1));
        tm1 = fmaxf(tm1, __shfl_xor_sync(0xffffffffu, tm1, 2));

        float mn0 = fmaxf(mrow[0], tm0), mn1 = fmaxf(mrow[1], tm1);
        float c0 = __expf(mrow[0] - mn0), c1 = __expf(mrow[1] - mn1);
        mrow[0] = mn0; mrow[1] = mn1;
        float nb0 = -mn0 * L2E, nb1 = -mn1 * L2E;

        // P fragments directly in registers (mma A-operand order)
        uint32_t pA[4][4];
        #pragma unroll
        for (int ks = 0; ks < 4; ks++) {
            int e = 2 * ks, o = 2 * ks + 1;
            pA[ks][0] = hex2(f2h2(fmaf(sacc[e][0], L2E, nb0), fmaf(sacc[e][1], L2E, nb0)));
            pA[ks][1] = hex2(f2h2(fmaf(sacc[e][2], L2E, nb1), fmaf(sacc[e][3], L2E, nb1)));
            pA[ks][2] = hex2(f2h2(fmaf(sacc[o][0], L2E, nb0), fmaf(sacc[o][1], L2E, nb0)));
            pA[ks][3] = hex2(f2h2(fmaf(sacc[o][2], L2E, nb1), fmaf(sacc[o][3], L2E, nb1)));
        }

        // rescale accumulators (sum column gets same treatment)
        #pragma unroll
        for (int df = 0; df < 8; df++) {
            oacc[df][0] *= c0; oacc[df][1] *= c0;
            oacc[df][2] *= c1; oacc[df][3] *= c1;
        }
        sumacc[0] *= c0; sumacc[1] *= c0;
        sumacc[2] *= c1; sumacc[3] *= c1;

        // ---- O += P V ; l += P @ 1 ----
        #pragma unroll
        for (int ks = 0; ks < 4; ks++) {
            mma_f16(sumacc, pA[ks][0], pA[ks][1], pA[ks][2], pA[ks][3], ONE2, ONE2);
            #pragma unroll
            for (int df = 0; df < 8; df++) {
                uint2 vb = Vp[(ks * 4 + tig) * VP_S + df * 8 + g];
                mma_f16(oacc[df], pA[ks][0], pA[ks][1], pA[ks][2], pA[ks][3], vb.x, vb.y);
            }
        }
    }

    // ---- epilogue: normalize + residual ----
    float inv0 = 1.0f / sumacc[0], inv1 = 1.0f / sumacc[2];
    int r = q0 + wrow + g;
    #pragma unroll
    for (int df = 0; df < 8; df++) {
        size_t idx0 = ((size_t)(b * SEQ + r)) * D_MODEL + h * DKH + df * 8 + 2 * tig;
        size_t idx1 = idx0 + (size_t)8 * D_MODEL;
        float2 ra = *(const float2*)(res + idx0);
        float2 rb = *(const float2*)(res + idx1);
        float2 oa, ob;
        oa.x = ra.x + oacc[df][0] * inv0;
        oa.y = ra.y + oacc[df][1] * inv0;
        ob.x = rb.x + oacc[df][2] * inv1;
        ob.y = rb.y + oacc[df][3] * inv1;
        *(float2*)(out + idx0) = oa;
        *(float2*)(out + idx1) = ob;
    }
}

// ---------------------------------------------------------------------------
// fp16 mma GEMM, fp16 inputs: C = A @ B + bias (+ReLU), out fp32 or fp16.
// Block 128x128, BK=32, 256 threads, warp tile 16x128. Pipelined.
// ---------------------------------------------------------------------------
#define GA_S 12
#define GB_S 132

template<bool RELU, bool RES, bool HOUT>
__global__ __launch_bounds__(256, 2)
void gemm_mma(const uint32_t* __restrict__ A,   // fp16 pairs, [M][K/2]
              const uint32_t* __restrict__ B,   // fp16 pairs, [K][N/2]
              const float* __restrict__ bias,
              const float* __restrict__ res,
              void* __restrict__ Cv,
              int M, int N, int K) {
    __shared__ uint2 Ap[128 * GA_S];
    __shared__ uint2 Bp[8 * GB_S];

    const int n0   = blockIdx.x * 128;
    const int m0   = blockIdx.y * 128;
    const int tid  = threadIdx.x;
    const int lane = tid & 31;
    const int warp = tid >> 5;
    const int g    = lane >> 2;
    const int tig  = lane & 3;
    const int wrow = warp * 16;
    const int KU   = K / 2, NU = N / 2;

    const int ar  = tid >> 1, ah = tid & 1;
    const int bcc = tid & 31;
    const int bks = (tid >> 7) & 1, btr = (tid >> 5) & 3;
    const int br0 = bks * 16 + 2 * btr;

    uint4 af[2];
    uint2 bf[4];

    auto ldg_tiles = [&](int k0) {
        const uint32_t* as_ = A + (size_t)(m0 + ar) * KU + k0 / 2 + ah * 8;
        af[0] = *(const uint4*)as_;
        af[1] = *(const uint4*)(as_ + 4);
        const uint32_t* bs_ = B + (size_t)(k0 + br0) * NU + n0 / 2 + bcc * 2;
        bf[0] = *(const uint2*)bs_;
        bf[1] = *(const uint2*)(bs_ + (size_t)1 * NU);
        bf[2] = *(const uint2*)(bs_ + (size_t)8 * NU);
        bf[3] = *(const uint2*)(bs_ + (size_t)9 * NU);
    };
    auto sts_tiles = [&]() {
        uint4* da = (uint4*)(Ap + ar * GA_S + ah * 4);
        da[0] = make_uint4(af[0].x, af[1].x, af[0].y, af[1].y);
        da[1] = make_uint4(af[0].z, af[1].z, af[0].w, af[1].w);
        uint4* db = (uint4*)(Bp + (bks * 4 + btr) * GB_S + bcc * 4);
        db[0] = make_uint4(h2lo(bf[0].x, bf[1].x), h2lo(bf[2].x, bf[3].x),
                           h2hi(bf[0].x, bf[1].x), h2hi(bf[2].x, bf[3].x));
        db[1] = make_uint4(h2lo(bf[0].y, bf[1].y), h2lo(bf[2].y, bf[3].y),
                           h2hi(bf[0].y, bf[1].y), h2hi(bf[2].y, bf[3].y));
    };

    float acc[16][4];
    #pragma unroll
    for (int i = 0; i < 16; i++)
        #pragma unroll
        for (int j = 0; j < 4; j++) acc[i][j] = 0.0f;

    ldg_tiles(0);

    for (int k0 = 0; k0 < K; k0 += 32) {
        __syncthreads();
        sts_tiles();
        __syncthreads();
        if (k0 + 32 < K) ldg_tiles(k0 + 32);

        #pragma unroll
        for (int ks = 0; ks < 2; ks++) {
            uint2 aa = Ap[(wrow + g)     * GA_S + ks * 4 + tig];
            uint2 ab = Ap[(wrow + 8 + g) * GA_S + ks * 4 + tig];
            #pragma unroll
            for (int nf = 0; nf < 16; nf++) {
                uint2 bb = Bp[(ks * 4 + tig) * GB_S + nf * 8 + g];
                mma_f16(acc[nf], aa.x, ab.x, aa.y, ab.y, bb.x, bb.y);
            }
        }
    }

    const int row0 = m0 + wrow + g;
    #pragma unroll
    for (int nf = 0; nf < 16; nf++) {
        int col = n0 + nf * 8 + 2 * tig;
        float2 bi = *(const float2*)(bias + col);
        float2 va, vb;
        va.x = acc[nf][0] + bi.x; va.y = acc[nf][1] + bi.y;
        vb.x = acc[nf][2] + bi.x; vb.y = acc[nf][3] + bi.y;
        if (RELU) {
            va.x = fmaxf(va.x, 0.0f); va.y = fmaxf(va.y, 0.0f);
            vb.x = fmaxf(vb.x, 0.0f); vb.y = fmaxf(vb.y, 0.0f);
        }
        if (HOUT) {
            uint32_t* C = (uint32_t*)Cv;
            C[((size_t)row0 * N + col) / 2]       = f2h2(va.x, va.y);
            C[((size_t)(row0 + 8) * N + col) / 2] = f2h2(vb.x, vb.y);
        } else {
            float* C = (float*)Cv;
            size_t idx0 = (size_t)row0 * N + col;
            size_t idx1 = idx0 + (size_t)8 * N;
            if (RES) {
                float2 ra = *(const float2*)(res + idx0);
                float2 rb = *(const float2*)(res + idx1);
                va.x += ra.x; va.y += ra.y;
                vb.x += rb.x; vb.y += rb.y;
            }
            *(float2*)(C + idx0) = va;
            *(float2*)(C + idx1) = vb;
        }
    }
}

// ---------------------------------------------------------------------------
extern "C" void kernel_launch(void* const* d_in, const int* in_sizes, int n_in,
                              void* d_out, int out_size) {
    const float* x    = (const float*)d_in[0];
    const float* enc  = (const float*)d_in[1];
    const int*   mask = (const int*)  d_in[2];
    const float* ln1g = (const float*)d_in[3];
    const float* ln1b = (const float*)d_in[4];
    const float* ln2g = (const float*)d_in[5];
    const float* ln2b = (const float*)d_in[6];
    const float* ln3g = (const float*)d_in[7];
    const float* ln3b = (const float*)d_in[8];
    const float* W1   = (const float*)d_in[9];
    const float* b1   = (const float*)d_in[10];
    const float* W2   = (const float*)d_in[11];
    const float* b2   = (const float*)d_in[12];
    float* out = (float*)d_out;

    float *gx;
    uint32_t *gxnh, *gench, *ghh, *gw1h, *gw2h, *gpm;
    cudaGetSymbolAddress((void**)&gx,    g_x);
    cudaGetSymbolAddress((void**)&gxnh,  g_xnh);
    cudaGetSymbolAddress((void**)&gench, g_ench);
    cudaGetSymbolAddress((void**)&ghh,   g_hh);
    cudaGetSymbolAddress((void**)&gw1h,  g_w1h);
    cudaGetSymbolAddress((void**)&gw2h,  g_w2h);
    cudaGetSymbolAddress((void**)&gpm,   g_pm);

    cudaFuncSetAttribute(attn_mma_kernel,
                         cudaFuncAttributeMaxDynamicSharedMemorySize,
                         ATTN_SMEM_BYTES);

    dim3 attn_grid(SEQ / BM, HEADS, BATCH);

    // one-time conversions (per launch)
    pack_mask_kernel<<<(BATCH * SEQ * SEQ) / 1024 / 8, 256>>>(mask, gpm);
    cvt_h_kernel<<<2048, 256>>>(enc, gench, NROWS * D_MODEL / 4);
    cvt_h_kernel<<<512,  256>>>(W1,  gw1h,  D_MODEL * D_FF / 4);
    cvt_h_kernel<<<512,  256>>>(W2,  gw2h,  D_FF * D_MODEL / 4);

    // 1) x1 = LN1(x); x' = x + selfattn(x1, mask)
    ln_kernel<<<NROWS, 128>>>(x, ln1g, ln1b, gxnh);
    attn_mma_kernel<<<attn_grid, 256, ATTN_SMEM_BYTES>>>(gxnh, gxnh, gpm, x, gx);

    // 2) x1 = LN2(x'); x'' = x' + crossattn(x1, enc)
    ln_kernel<<<NROWS, 128>>>(gx, ln2g, ln2b, gxnh);
    attn_mma_kernel<<<attn_grid, 256, ATTN_SMEM_BYTES>>>(gxnh, gench, nullptr, gx, gx);

    // 3) x1 = LN3(x''); out = x'' + relu(x1 W1 + b1) W2 + b2
    ln_kernel<<<NROWS, 128>>>(gx, ln3g, ln3b, gxnh);
    gemm_mma<true,  false, true ><<<dim3(D_FF / 128,    NROWS / 128), 256>>>(
        gxnh, gw1h, b1, nullptr, ghh, NROWS, D_FF, D_MODEL);
    gemm_mma<false, true,  false><<<dim3(D_MODEL / 128, NROWS / 128), 256>>>(
        ghh, gw2h, b2, gx, out, NROWS, D_MODEL, D_FF);
}

// round 13
// speedup vs baseline: 2.2885x; 1.0153x over previous
#include <cuda_runtime.h>
#include <cuda_fp16.h>
#include <math.h>
#include <stdint.h>

#define D_MODEL 512
#define HEADS   8
#define DKH     64
#define SEQ     2048
#define BATCH   4
#define D_FF    1024
#define NROWS   (BATCH*SEQ)   // 8192

// Scratch (static device arrays — no allocation at runtime)
__device__ float    g_x  [NROWS * D_MODEL];          // residual stream (fp32)
__device__ uint32_t g_xnh[NROWS * D_MODEL / 2];      // LN output, fp16 pairs
__device__ uint32_t g_ench[NROWS * D_MODEL / 2];     // encoder_output fp16
__device__ uint32_t g_hh [NROWS * D_FF / 2];         // FFN hidden fp16
__device__ uint32_t g_w1h[D_MODEL * D_FF / 2];       // W1 fp16
__device__ uint32_t g_w2h[D_FF * D_MODEL / 2];       // W2 fp16
__device__ uint32_t g_pm [BATCH * SEQ * (SEQ / 32)]; // packed mask bits (2MB)

// ---------------------------------------------------------------------------
// helpers
// ---------------------------------------------------------------------------
__device__ __forceinline__ uint32_t f2h2(float lo, float hi) {
    __half2 h = __floats2half2_rn(lo, hi);
    return *(uint32_t*)&h;
}
__device__ __forceinline__ uint32_t h2lo(uint32_t a, uint32_t b) {  // {a.h0,b.h0}
    return __byte_perm(a, b, 0x5410);
}
__device__ __forceinline__ uint32_t h2hi(uint32_t a, uint32_t b) {  // {a.h1,b.h1}
    return __byte_perm(a, b, 0x7632);
}
__device__ __forceinline__ uint32_t hex2(uint32_t t) {   // 2^t per fp16 lane
    uint32_t r;
    asm("ex2.approx.f16x2 %0, %1;" : "=r"(r) : "r"(t));
    return r;
}

__device__ __forceinline__ void mma_f16(float c[4],
                                        uint32_t a0, uint32_t a1, uint32_t a2, uint32_t a3,
                                        uint32_t b0, uint32_t b1) {
    asm volatile(
        "mma.sync.aligned.m16n8k16.row.col.f32.f16.f16.f32 "
        "{%0,%1,%2,%3}, {%4,%5,%6,%7}, {%8,%9}, {%0,%1,%2,%3};\n"
        : "+f"(c[0]), "+f"(c[1]), "+f"(c[2]), "+f"(c[3])
        : "r"(a0), "r"(a1), "r"(a2), "r"(a3), "r"(b0), "r"(b1));
}

#define L2E 1.4426950408889634f
#define ONE2 0x3C003C00u   // fp16 {1.0, 1.0}

// ---------------------------------------------------------------------------
// fp32 -> fp16 pair converter (grid-stride, float4 -> uint2)
// ---------------------------------------------------------------------------
__global__ void cvt_h_kernel(const float* __restrict__ x,
                             uint32_t* __restrict__ yh, int n4) {
    int i = blockIdx.x * blockDim.x + threadIdx.x;
    int stride = gridDim.x * blockDim.x;
    for (; i < n4; i += stride) {
        float4 v = ((const float4*)x)[i];
        ((uint2*)yh)[i] = make_uint2(f2h2(v.x, v.y), f2h2(v.z, v.w));
    }
}

// ---------------------------------------------------------------------------
// Mask packing: bit j of pm[i/32] = (mask[i] != 0). 1 warp handles 1024 ints.
// ---------------------------------------------------------------------------
__device__ __forceinline__ uint32_t spread4(uint32_t x) {
    x &= 0xFFu;
    x = (x | (x << 12)) & 0x000F000Fu;
    x = (x | (x << 6))  & 0x03030303u;
    x = (x | (x << 3))  & 0x11111111u;
    return x;
}

__global__ void pack_mask_kernel(const int* __restrict__ mask,
                                 uint32_t* __restrict__ pm) {
    int w    = (blockIdx.x * blockDim.x + threadIdx.x) >> 5;
    int lane = threadIdx.x & 31;
    size_t base = (size_t)w * 1024;
    #pragma unroll
    for (int it = 0; it < 8; it++) {
        int4 v = *(const int4*)(mask + base + it * 128 + lane * 4);
        uint32_t b0 = __ballot_sync(0xffffffffu, v.x != 0);
        uint32_t b1 = __ballot_sync(0xffffffffu, v.y != 0);
        uint32_t b2 = __ballot_sync(0xffffffffu, v.z != 0);
        uint32_t b3 = __ballot_sync(0xffffffffu, v.w != 0);
        if (lane < 4) {
            uint32_t word =  spread4(b0 >> (8 * lane))
                          | (spread4(b1 >> (8 * lane)) << 1)
                          | (spread4(b2 >> (8 * lane)) << 2)
                          | (spread4(b3 >> (8 * lane)) << 3);
            pm[base / 32 + it * 4 + lane] = word;
        }
    }
}

// ---------------------------------------------------------------------------
// LayerNorm: one WARP per row (512 elems = 16 floats/lane), shuffle-only
// reduction, no smem, no block barriers. Block 256 = 8 rows. Emits fp16 pairs.
// ---------------------------------------------------------------------------
__global__ __launch_bounds__(256)
void ln_kernel(const float* __restrict__ x,
               const float* __restrict__ gamma,
               const float* __restrict__ beta,
               uint32_t* __restrict__ yh) {
    const int lane = threadIdx.x & 31;
    const int row  = blockIdx.x * 8 + (threadIdx.x >> 5);
    const float4* xr = (const float4*)(x + (size_t)row * D_MODEL);

    float4 v[4];
    float s = 0.0f, ss = 0.0f;
    #pragma unroll
    for (int i = 0; i < 4; i++) {
        v[i] = xr[lane + 32 * i];
        s  += v[i].x + v[i].y + v[i].z + v[i].w;
        ss += v[i].x*v[i].x + v[i].y*v[i].y + v[i].z*v[i].z + v[i].w*v[i].w;
    }
    #pragma unroll
    for (int o = 16; o > 0; o >>= 1) {
        s  += __shfl_xor_sync(0xffffffffu, s,  o);
        ss += __shfl_xor_sync(0xffffffffu, ss, o);
    }
    float mu  = s * (1.0f / D_MODEL);
    float var = ss * (1.0f / D_MODEL) - mu * mu;
    float rs  = rsqrtf(var + 1e-5f);

    uint2* yr = (uint2*)(yh + (size_t)row * (D_MODEL / 2));
    #pragma unroll
    for (int i = 0; i < 4; i++) {
        float4 g4 = ((const float4*)gamma)[lane + 32 * i];
        float4 b4 = ((const float4*)beta)[lane + 32 * i];
        float o0 = (v[i].x - mu) * rs * g4.x + b4.x;
        float o1 = (v[i].y - mu) * rs * g4.y + b4.y;
        float o2 = (v[i].z - mu) * rs * g4.z + b4.z;
        float o3 = (v[i].w - mu) * rs * g4.w + b4.w;
        yr[lane + 32 * i] = make_uint2(f2h2(o0, o1), f2h2(o2, o3));
    }
}

// ---------------------------------------------------------------------------
// Flash attention, fp16 mma. BM=128, 256 threads, warp tile 16x64.
// Register-resident P, ex2.f16x2 softmax, ones-mma row-sum,
// double-buffered K/V (1 barrier/tile). (R11 validated path — unchanged.)
// ---------------------------------------------------------------------------
#define BM    128
#define QP_S  20
#define KP_S  20
#define VP_S  68
#define KSTG  (64*KP_S + 16*VP_S)    // uint2 per K/V stage
#define ATTN_SMEM_BYTES ((128*QP_S + 2*KSTG) * 8)
#define ROWU  (D_MODEL / 2)          // u32 per row (256)

__global__ __launch_bounds__(256, 2)
void attn_mma_kernel(const uint32_t* __restrict__ Qh,
                     const uint32_t* __restrict__ KVh,
                     const uint32_t* __restrict__ pm,   // packed mask, may be null
                     const float* __restrict__ res,
                     float* __restrict__ out) {
    extern __shared__ uint2 sm2[];
    uint2* Qp     = sm2;
    uint2* KVbase = Qp + 128 * QP_S;

    const int q0   = blockIdx.x * BM;
    const int h    = blockIdx.y;
    const int b    = blockIdx.z;
    const int tid  = threadIdx.x;
    const int lane = tid & 31;
    const int warp = tid >> 5;
    const int g    = lane >> 2;
    const int tig  = lane & 3;
    const int wrow = warp * 16;

    const __half2 qscale = __float2half2_rn(0.125f);   // exact (power of 2)

    #pragma unroll
    for (int it = 0; it < 2; it++) {
        int i = tid + it * 256;
        int r = i >> 2, cc = i & 3;
        const uint32_t* src = Qh + (size_t)(b * SEQ + q0 + r) * ROWU + h * 32 + cc * 8;
        uint4 u0 = *(const uint4*)src;
        uint4 u1 = *(const uint4*)(src + 4);
        uint32_t u[8] = {u0.x, u0.y, u0.z, u0.w, u1.x, u1.y, u1.z, u1.w};
        #pragma unroll
        for (int k = 0; k < 8; k++) {
            __half2 hv = __hmul2(*(__half2*)&u[k], qscale);
            u[k] = *(uint32_t*)&hv;
        }
        uint4* d4 = (uint4*)(Qp + r * QP_S + cc * 4);
        d4[0] = make_uint4(u[0], u[4], u[1], u[5]);
        d4[1] = make_uint4(u[2], u[6], u[3], u[7]);
    }

    float oacc[8][4];
    #pragma unroll
    for (int i = 0; i < 8; i++)
        #pragma unroll
        for (int j = 0; j < 4; j++) oacc[i][j] = 0.0f;
    float sumacc[4] = {0.0f, 0.0f, 0.0f, 0.0f};

    float mrow[2] = {-INFINITY, -INFINITY};

    const int kr  = tid >> 2,  kcc = tid & 3;
    const int vcc = tid & 15;
    const int vks = (tid >> 6) & 3, vtr = (tid >> 4) & 3;
    const int vr0 = vks * 16 + 2 * vtr;

    uint4 kf[2];
    uint2 vf[4];

    auto ldg_tile = [&](int k0) {
        const uint32_t* ks_ = KVh + (size_t)(b * SEQ + k0 + kr) * ROWU + h * 32 + kcc * 8;
        kf[0] = *(const uint4*)ks_;
        kf[1] = *(const uint4*)(ks_ + 4);
        const uint32_t* vs_ = KVh + (size_t)(b * SEQ + k0 + vr0) * ROWU + h * 32 + vcc * 2;
        vf[0] = *(const uint2*)vs_;
        vf[1] = *(const uint2*)(vs_ + (size_t)1 * ROWU);
        vf[2] = *(const uint2*)(vs_ + (size_t)8 * ROWU);
        vf[3] = *(const uint2*)(vs_ + (size_t)9 * ROWU);
    };
    auto sts_tile = [&](uint2* Kp, uint2* Vp) {
        uint4* dk = (uint4*)(Kp + kr * KP_S + kcc * 4);
        dk[0] = make_uint4(kf[0].x, kf[1].x, kf[0].y, kf[1].y);
        dk[1] = make_uint4(kf[0].z, kf[1].z, kf[0].w, kf[1].w);
        uint4* dv = (uint4*)(Vp + (vks * 4 + vtr) * VP_S + vcc * 4);
        dv[0] = make_uint4(h2lo(vf[0].x, vf[1].x), h2lo(vf[2].x, vf[3].x),
                           h2hi(vf[0].x, vf[1].x), h2hi(vf[2].x, vf[3].x));
        dv[1] = make_uint4(h2lo(vf[0].y, vf[1].y), h2lo(vf[2].y, vf[3].y),
                           h2hi(vf[0].y, vf[1].y), h2hi(vf[2].y, vf[3].y));
    };

    ldg_tile(0);

    for (int kt = 0; kt < SEQ / 64; kt++) {
        uint2* Kp = KVbase + (kt & 1) * KSTG;
        uint2* Vp = Kp + 64 * KP_S;
        sts_tile(Kp, Vp);
        __syncthreads();
        if (kt + 1 < SEQ / 64) ldg_tile((kt + 1) * 64);

        uint2 pmA, pmB;
        if (pm != nullptr) {
            const uint32_t* pr = pm + ((size_t)(b * SEQ + q0 + wrow + g)) * (SEQ / 32) + kt * 2;
            pmA = *(const uint2*)pr;
            pmB = *(const uint2*)(pr + (size_t)8 * (SEQ / 32));
        }

        float sacc[8][4];
        #pragma unroll
        for (int i = 0; i < 8; i++)
            #pragma unroll
            for (int j = 0; j < 4; j++) sacc[i][j] = 0.0f;

        #pragma unroll
        for (int ks = 0; ks < 4; ks++) {
            uint2 qa = Qp[(wrow + g)     * QP_S + ks * 4 + tig];
            uint2 qb = Qp[(wrow + 8 + g) * QP_S + ks * 4 + tig];
            #pragma unroll
            for (int nf = 0; nf < 8; nf++) {
                uint2 kb = Kp[(nf * 8 + g) * KP_S + ks * 4 + tig];
                mma_f16(sacc[nf], qa.x, qb.x, qa.y, qb.y, kb.x, kb.y);
            }
        }

        if (pm != nullptr) {
            #pragma unroll
            for (int nf = 0; nf < 8; nf++) {
                uint32_t wA = (nf < 4) ? pmA.x : pmA.y;
                uint32_t wB = (nf < 4) ? pmB.x : pmB.y;
                int sh = ((nf & 3) * 8) + 2 * tig;
                if (!((wA >> sh) & 1u)) sacc[nf][0] = -1e9f;
                if (!((wA >> sh) & 2u)) sacc[nf][1] = -1e9f;
                if (!((wB >> sh) & 1u)) sacc[nf][2] = -1e9f;
                if (!((wB >> sh) & 2u)) sacc[nf][3] = -1e9f;
            }
        }

        float tm0 = -INFINITY, tm1 = -INFINITY;
        #pragma unroll
        for (int nf = 0; nf < 8; nf++) {
            tm0 = fmaxf(tm0, fmaxf(sacc[nf][0], sacc[nf][1]));
            tm1 = fmaxf(tm1, fmaxf(sacc[nf][2], sacc[nf][3]));
        }
        tm0 = fmaxf(tm0, __shfl_xor_sync(0xffffffffu, tm0, 1));
        tm0 = fmaxf(tm0, __shfl_xor_sync(0xffffffffu, tm0, 2));
        tm1 = fmaxf(tm1, __shfl_xor_sync(0xffffffffu, tm1, 1));
        tm1 = fmaxf(tm1, __shfl_xor_sync(0xffffffffu, tm1, 2));

        float mn0 = fmaxf(mrow[0], tm0), mn1 = fmaxf(mrow[1], tm1);
        float c0 = __expf(mrow[0] - mn0), c1 = __expf(mrow[1] - mn1);
        mrow[0] = mn0; mrow[1] = mn1;
        float nb0 = -mn0 * L2E, nb1 = -mn1 * L2E;

        uint32_t pA[4][4];
        #pragma unroll
        for (int ks = 0; ks < 4; ks++) {
            int e = 2 * ks, o = 2 * ks + 1;
            pA[ks][0] = hex2(f2h2(fmaf(sacc[e][0], L2E, nb0), fmaf(sacc[e][1], L2E, nb0)));
            pA[ks][1] = hex2(f2h2(fmaf(sacc[e][2], L2E, nb1), fmaf(sacc[e][3], L2E, nb1)));
            pA[ks][2] = hex2(f2h2(fmaf(sacc[o][0], L2E, nb0), fmaf(sacc[o][1], L2E, nb0)));
            pA[ks][3] = hex2(f2h2(fmaf(sacc[o][2], L2E, nb1), fmaf(sacc[o][3], L2E, nb1)));
        }

        #pragma unroll
        for (int df = 0; df < 8; df++) {
            oacc[df][0] *= c0; oacc[df][1] *= c0;
            oacc[df][2] *= c1; oacc[df][3] *= c1;
        }
        sumacc[0] *= c0; sumacc[1] *= c0;
        sumacc[2] *= c1; sumacc[3] *= c1;

        #pragma unroll
        for (int ks = 0; ks < 4; ks++) {
            mma_f16(sumacc, pA[ks][0], pA[ks][1], pA[ks][2], pA[ks][3], ONE2, ONE2);
            #pragma unroll
            for (int df = 0; df < 8; df++) {
                uint2 vb = Vp[(ks * 4 + tig) * VP_S + df * 8 + g];
                mma_f16(oacc[df], pA[ks][0], pA[ks][1], pA[ks][2], pA[ks][3], vb.x, vb.y);
            }
        }
    }

    float inv0 = 1.0f / sumacc[0], inv1 = 1.0f / sumacc[2];
    int r = q0 + wrow + g;
    #pragma unroll
    for (int df = 0; df < 8; df++) {
        size_t idx0 = ((size_t)(b * SEQ + r)) * D_MODEL + h * DKH + df * 8 + 2 * tig;
        size_t idx1 = idx0 + (size_t)8 * D_MODEL;
        float2 ra = *(const float2*)(res + idx0);
        float2 rb = *(const float2*)(res + idx1);
        float2 oa, ob;
        oa.x = ra.x + oacc[df][0] * inv0;
        oa.y = ra.y + oacc[df][1] * inv0;
        ob.x = rb.x + oacc[df][2] * inv1;
        ob.y = rb.y + oacc[df][3] * inv1;
        *(float2*)(out + idx0) = oa;
        *(float2*)(out + idx1) = ob;
    }
}

// ---------------------------------------------------------------------------
// fp16 mma GEMM, fp16 inputs: C = A @ B + bias (+ReLU), out fp32 or fp16.
// Block 128x128, BK=32, 256 threads, warp tile 16x128.
// Double-buffered smem: ONE __syncthreads per k-step.
// ---------------------------------------------------------------------------
#define GA_S 12
#define GB_S 132
#define ASTG (128 * GA_S)
#define BSTG (8 * GB_S)

template<bool RELU, bool RES, bool HOUT>
__global__ __launch_bounds__(256, 2)
void gemm_mma(const uint32_t* __restrict__ A,   // fp16 pairs, [M][K/2]
              const uint32_t* __restrict__ B,   // fp16 pairs, [K][N/2]
              const float* __restrict__ bias,
              const float* __restrict__ res,
              void* __restrict__ Cv,
              int M, int N, int K) {
    __shared__ uint2 Apb[2 * ASTG];
    __shared__ uint2 Bpb[2 * BSTG];

    const int n0   = blockIdx.x * 128;
    const int m0   = blockIdx.y * 128;
    const int tid  = threadIdx.x;
    const int lane = tid & 31;
    const int warp = tid >> 5;
    const int g    = lane >> 2;
    const int tig  = lane & 3;
    const int wrow = warp * 16;
    const int KU   = K / 2, NU = N / 2;

    const int ar  = tid >> 1, ah = tid & 1;
    const int bcc = tid & 31;
    const int bks = (tid >> 7) & 1, btr = (tid >> 5) & 3;
    const int br0 = bks * 16 + 2 * btr;

    uint4 af[2];
    uint2 bf[4];

    auto ldg_tiles = [&](int k0) {
        const uint32_t* as_ = A + (size_t)(m0 + ar) * KU + k0 / 2 + ah * 8;
        af[0] = *(const uint4*)as_;
        af[1] = *(const uint4*)(as_ + 4);
        const uint32_t* bs_ = B + (size_t)(k0 + br0) * NU + n0 / 2 + bcc * 2;
        bf[0] = *(const uint2*)bs_;
        bf[1] = *(const uint2*)(bs_ + (size_t)1 * NU);
        bf[2] = *(const uint2*)(bs_ + (size_t)8 * NU);
        bf[3] = *(const uint2*)(bs_ + (size_t)9 * NU);
    };
    auto sts_tiles = [&](uint2* Ap, uint2* Bp) {
        uint4* da = (uint4*)(Ap + ar * GA_S + ah * 4);
        da[0] = make_uint4(af[0].x, af[1].x, af[0].y, af[1].y);
        da[1] = make_uint4(af[0].z, af[1].z, af[0].w, af[1].w);
        uint4* db = (uint4*)(Bp + (bks * 4 + btr) * GB_S + bcc * 4);
        db[0] = make_uint4(h2lo(bf[0].x, bf[1].x), h2lo(bf[2].x, bf[3].x),
                           h2hi(bf[0].x, bf[1].x), h2hi(bf[2].x, bf[3].x));
        db[1] = make_uint4(h2lo(bf[0].y, bf[1].y), h2lo(bf[2].y, bf[3].y),
                           h2hi(bf[0].y, bf[1].y), h2hi(bf[2].y, bf[3].y));
    };

    float acc[16][4];
    #pragma unroll
    for (int i = 0; i < 16; i++)
        #pragma unroll
        for (int j = 0; j < 4; j++) acc[i][j] = 0.0f;

    ldg_tiles(0);

    int it = 0;
    for (int k0 = 0; k0 < K; k0 += 32, it++) {
        uint2* Ap = Apb + (it & 1) * ASTG;
        uint2* Bp = Bpb + (it & 1) * BSTG;
        sts_tiles(Ap, Bp);
        __syncthreads();   // stage (it&1) ready; prev compute on other buffer done
        if (k0 + 32 < K) ldg_tiles(k0 + 32);

        #pragma unroll
        for (int ks = 0; ks < 2; ks++) {
            uint2 aa = Ap[(wrow + g)     * GA_S + ks * 4 + tig];
            uint2 ab = Ap[(wrow + 8 + g) * GA_S + ks * 4 + tig];
            #pragma unroll
            for (int nf = 0; nf < 16; nf++) {
                uint2 bb = Bp[(ks * 4 + tig) * GB_S + nf * 8 + g];
                mma_f16(acc[nf], aa.x, ab.x, aa.y, ab.y, bb.x, bb.y);
            }
        }
    }

    const int row0 = m0 + wrow + g;
    #pragma unroll
    for (int nf = 0; nf < 16; nf++) {
        int col = n0 + nf * 8 + 2 * tig;
        float2 bi = *(const float2*)(bias + col);
        float2 va, vb;
        va.x = acc[nf][0] + bi.x; va.y = acc[nf][1] + bi.y;
        vb.x = acc[nf][2] + bi.x; vb.y = acc[nf][3] + bi.y;
        if (RELU) {
            va.x = fmaxf(va.x, 0.0f); va.y = fmaxf(va.y, 0.0f);
            vb.x = fmaxf(vb.x, 0.0f); vb.y = fmaxf(vb.y, 0.0f);
        }
        if (HOUT) {
            uint32_t* C = (uint32_t*)Cv;
            C[((size_t)row0 * N + col) / 2]       = f2h2(va.x, va.y);
            C[((size_t)(row0 + 8) * N + col) / 2] = f2h2(vb.x, vb.y);
        } else {
            float* C = (float*)Cv;
            size_t idx0 = (size_t)row0 * N + col;
            size_t idx1 = idx0 + (size_t)8 * N;
            if (RES) {
                float2 ra = *(const float2*)(res + idx0);
                float2 rb = *(const float2*)(res + idx1);
                va.x += ra.x; va.y += ra.y;
                vb.x += rb.x; vb.y += rb.y;
            }
            *(float2*)(C + idx0) = va;
            *(float2*)(C + idx1) = vb;
        }
    }
}

// ---------------------------------------------------------------------------
extern "C" void kernel_launch(void* const* d_in, const int* in_sizes, int n_in,
                              void* d_out, int out_size) {
    const float* x    = (const float*)d_in[0];
    const float* enc  = (const float*)d_in[1];
    const int*   mask = (const int*)  d_in[2];
    const float* ln1g = (const float*)d_in[3];
    const float* ln1b = (const float*)d_in[4];
    const float* ln2g = (const float*)d_in[5];
    const float* ln2b = (const float*)d_in[6];
    const float* ln3g = (const float*)d_in[7];
    const float* ln3b = (const float*)d_in[8];
    const float* W1   = (const float*)d_in[9];
    const float* b1   = (const float*)d_in[10];
    const float* W2   = (const float*)d_in[11];
    const float* b2   = (const float*)d_in[12];
    float* out = (float*)d_out;

    float *gx;
    uint32_t *gxnh, *gench, *ghh, *gw1h, *gw2h, *gpm;
    cudaGetSymbolAddress((void**)&gx,    g_x);
    cudaGetSymbolAddress((void**)&gxnh,  g_xnh);
    cudaGetSymbolAddress((void**)&gench, g_ench);
    cudaGetSymbolAddress((void**)&ghh,   g_hh);
    cudaGetSymbolAddress((void**)&gw1h,  g_w1h);
    cudaGetSymbolAddress((void**)&gw2h,  g_w2h);
    cudaGetSymbolAddress((void**)&gpm,   g_pm);

    cudaFuncSetAttribute(attn_mma_kernel,
                         cudaFuncAttributeMaxDynamicSharedMemorySize,
                         ATTN_SMEM_BYTES);

    dim3 attn_grid(SEQ / BM, HEADS, BATCH);

    // one-time conversions (per launch)
    pack_mask_kernel<<<(BATCH * SEQ * SEQ) / 1024 / 8, 256>>>(mask, gpm);
    cvt_h_kernel<<<4096, 256>>>(enc, gench, NROWS * D_MODEL / 4);
    cvt_h_kernel<<<512,  256>>>(W1,  gw1h,  D_MODEL * D_FF / 4);
    cvt_h_kernel<<<512,  256>>>(W2,  gw2h,  D_FF * D_MODEL / 4);

    // 1) x1 = LN1(x); x' = x + selfattn(x1, mask)
    ln_kernel<<<NROWS / 8, 256>>>(x, ln1g, ln1b, gxnh);
    attn_mma_kernel<<<attn_grid, 256, ATTN_SMEM_BYTES>>>(gxnh, gxnh, gpm, x, gx);

    // 2) x1 = LN2(x'); x'' = x' + crossattn(x1, enc)
    ln_kernel<<<NROWS / 8, 256>>>(gx, ln2g, ln2b, gxnh);
    attn_mma_kernel<<<attn_grid, 256, ATTN_SMEM_BYTES>>>(gxnh, gench, nullptr, gx, gx);

    // 3) x1 = LN3(x''); out = x'' + relu(x1 W1 + b1) W2 + b2
    ln_kernel<<<NROWS / 8, 256>>>(gx, ln3g, ln3b, gxnh);
    gemm_mma<true,  false, true ><<<dim3(D_FF / 128,    NROWS / 128), 256>>>(
        gxnh, gw1h, b1, nullptr, ghh, NROWS, D_FF, D_MODEL);
    gemm_mma<false, true,  false><<<dim3(D_MODEL / 128, NROWS / 128), 256>>>(
        ghh, gw2h, b2, gx, out, NROWS, D_MODEL, D_FF);
}